// round 3
// baseline (speedup 1.0000x reference)
#include <cuda_runtime.h>
#include <math.h>

#define Bq 4
#define Nn 256
#define Tt 128
#define Fin 64
#define Kk 8
#define Hh 256
#define Ee 8

// Scratch (module-level device globals; no runtime allocation)
__device__ float g_h[Bq * Nn * Tt * Hh];      // [b][j][t][hh]  134 MB
__device__ float g_agg[Bq * Tt * Nn * Hh];    // [b][t][i][hh]  134 MB
__device__ float g_AT[Kk * Nn * Nn];          // [k][j][i] normalized, transposed
__device__ float g_ATs[Bq * Kk * Nn * Nn];    // [b][k][j][i] = alpha[b][k] * g_AT
__device__ float g_ctx[Bq * Fin];
__device__ float g_alpha[Bq * Kk];

__device__ __forceinline__ float gelu_exact(float v) {
    return 0.5f * v * (1.0f + erff(v * 0.7071067811865476f));
}

__device__ __forceinline__ void cp_async16(void* s, const void* g) {
    unsigned saddr = (unsigned)__cvta_generic_to_shared(s);
    asm volatile("cp.async.cg.shared.global [%0], [%1], 16;\n" ::"r"(saddr), "l"(g));
}

// ---------------------------------------------------------------------------
// K1: ctx[b][f] = mean over (N,T) of x
// ---------------------------------------------------------------------------
__global__ void k_ctx(const float* __restrict__ x) {
    int b = blockIdx.x;
    int col = threadIdx.x & 63;
    int g = threadIdx.x >> 6;  // 0..7 (512 threads)
    const float* xb = x + (size_t)b * (Nn * Tt * Fin);
    float acc = 0.f;
    for (int r = g; r < Nn * Tt; r += 8)
        acc += xb[(size_t)r * Fin + col];
    __shared__ float part[8][64];
    part[g][col] = acc;
    __syncthreads();
    if (threadIdx.x < 64) {
        float s = 0.f;
#pragma unroll
        for (int q = 0; q < 8; q++) s += part[q][threadIdx.x];
        g_ctx[b * Fin + threadIdx.x] = s * (1.0f / (Nn * Tt));
    }
}

// ---------------------------------------------------------------------------
// K2: alpha[b][k] = sigmoid(gate MLP([lag_emb[k], ctx_feat[b]]))
// ---------------------------------------------------------------------------
__global__ void k_alpha(const float* __restrict__ lag_embed,
                        const float* __restrict__ ctx_w1, const float* __restrict__ ctx_b1,
                        const float* __restrict__ ctx_w2, const float* __restrict__ ctx_b2,
                        const float* __restrict__ gate_w1, const float* __restrict__ gate_b1,
                        const float* __restrict__ gate_w2, const float* __restrict__ gate_b2) {
    int tid = threadIdx.x;
    if (tid >= Bq * Kk) return;
    int b = tid >> 3, k = tid & 7;
    float t1[Ee];
#pragma unroll
    for (int e = 0; e < Ee; e++) {
        float s = ctx_b1[e];
        for (int f = 0; f < Fin; f++) s += g_ctx[b * Fin + f] * ctx_w1[f * Ee + e];
        t1[e] = gelu_exact(s);
    }
    float cf[Ee];
#pragma unroll
    for (int e = 0; e < Ee; e++) {
        float s = ctx_b2[e];
#pragma unroll
        for (int q = 0; q < Ee; q++) s += t1[q] * ctx_w2[q * Ee + e];
        cf[e] = s;
    }
    float hg[Ee];
#pragma unroll
    for (int e = 0; e < Ee; e++) {
        float s = gate_b1[e];
#pragma unroll
        for (int q = 0; q < Ee; q++) s += lag_embed[k * Ee + q] * gate_w1[q * Ee + e];
#pragma unroll
        for (int q = 0; q < Ee; q++) s += cf[q] * gate_w1[(Ee + q) * Ee + e];
        hg[e] = gelu_exact(s);
    }
    float lg = gate_b2[0];
#pragma unroll
    for (int e = 0; e < Ee; e++) lg += hg[e] * gate_w2[e];
    g_alpha[b * Kk + k] = 1.f / (1.f + expf(-lg));
}

// ---------------------------------------------------------------------------
// K3: row-normalize A and store transposed: g_AT[k][j][i] = A[k][i][j]/rowsum
// ---------------------------------------------------------------------------
__global__ void k_anorm(const float* __restrict__ A) {
    int idx = blockIdx.x;  // k*256 + i
    int j = threadIdx.x;
    float v = A[(size_t)idx * Nn + j];
    __shared__ float red[Nn];
    red[j] = v;
    __syncthreads();
    for (int s = 128; s > 0; s >>= 1) {
        if (j < s) red[j] += red[j + s];
        __syncthreads();
    }
    float inv = 1.f / fmaxf(red[0], 1e-8f);
    int k = idx >> 8, i = idx & 255;
    g_AT[((size_t)(k * Nn + j)) * Nn + i] = v * inv;
}

// ---------------------------------------------------------------------------
// K3b: g_ATs[b][k][j][i] = alpha[b][k] * g_AT[k][j][i]
// ---------------------------------------------------------------------------
__global__ void k_ascale() {
    size_t idx = (size_t)blockIdx.x * blockDim.x + threadIdx.x;  // < 2^21
    int b = (int)(idx >> 19);
    int k = (int)((idx >> 16) & 7);
    g_ATs[idx] = g_alpha[b * Kk + k] * g_AT[idx & ((1u << 19) - 1u)];
}

// ---------------------------------------------------------------------------
// K4: h = x @ in_w + in_b   (M=131072, K=64, N=256) -> g_h (same row order)
// ---------------------------------------------------------------------------
__global__ __launch_bounds__(256) void k_ingemm(const float* __restrict__ x,
                                                const float* __restrict__ in_w,
                                                const float* __restrict__ in_b) {
    __shared__ __align__(16) float As[8][132];
    __shared__ __align__(16) float Bs[8][128];
    int m0 = blockIdx.y * 128;
    int n0 = blockIdx.x * 128;
    int tid = threadIdx.x;
    int tx = tid & 15, ty = tid >> 4;
    int lrowA = tid >> 1;
    int lk4 = (tid & 1) * 4;
    int lrowB = tid >> 5;
    int lc4 = (tid & 31) * 4;
    float acc[8][8] = {};
    for (int k0 = 0; k0 < Fin; k0 += 8) {
        float4 av = *(const float4*)(x + (size_t)(m0 + lrowA) * Fin + k0 + lk4);
        As[lk4 + 0][lrowA] = av.x;
        As[lk4 + 1][lrowA] = av.y;
        As[lk4 + 2][lrowA] = av.z;
        As[lk4 + 3][lrowA] = av.w;
        *(float4*)&Bs[lrowB][lc4] =
            *(const float4*)(in_w + (size_t)(k0 + lrowB) * Hh + n0 + lc4);
        __syncthreads();
#pragma unroll
        for (int kk = 0; kk < 8; kk++) {
            float4 a0 = *(const float4*)&As[kk][ty * 8];
            float4 a1 = *(const float4*)&As[kk][ty * 8 + 4];
            float4 b0 = *(const float4*)&Bs[kk][tx * 8];
            float4 b1 = *(const float4*)&Bs[kk][tx * 8 + 4];
            float ar[8] = {a0.x, a0.y, a0.z, a0.w, a1.x, a1.y, a1.z, a1.w};
            float br[8] = {b0.x, b0.y, b0.z, b0.w, b1.x, b1.y, b1.z, b1.w};
#pragma unroll
            for (int i = 0; i < 8; i++)
#pragma unroll
                for (int j = 0; j < 8; j++) acc[i][j] = fmaf(ar[i], br[j], acc[i][j]);
        }
        __syncthreads();
    }
#pragma unroll
    for (int i = 0; i < 8; i++) {
        int m = m0 + ty * 8 + i;
        float* outp = g_h + (size_t)m * Hh + n0 + tx * 8;
        float4 b0 = *(const float4*)(in_b + n0 + tx * 8);
        float4 b1 = *(const float4*)(in_b + n0 + tx * 8 + 4);
        float4 r0 = make_float4(acc[i][0] + b0.x, acc[i][1] + b0.y,
                                acc[i][2] + b0.z, acc[i][3] + b0.w);
        float4 r1 = make_float4(acc[i][4] + b1.x, acc[i][5] + b1.y,
                                acc[i][6] + b1.z, acc[i][7] + b1.w);
        *(float4*)outp = r0;
        *(float4*)(outp + 4) = r1;
    }
}

// ---------------------------------------------------------------------------
// K5: lag aggregation. Per (b,t):  agg[i,hh] = sum_{k,j} ATs[b][k][j][i]*h[b,j,t-k,hh]
// 128x128 tile, 8x8 micro, cp.async double-buffered over jk chunks of 8.
// ---------------------------------------------------------------------------
__global__ __launch_bounds__(256) void k_lag() {
    int bt = blockIdx.z;
    int b = bt >> 7;
    int t = bt & 127;
    int i0 = blockIdx.y * 128;
    int n0 = blockIdx.x * 128;
    __shared__ __align__(16) float As[2][8][128];
    __shared__ __align__(16) float Hs[2][8][128];
    int tid = threadIdx.x;
    int tx = tid & 15, ty = tid >> 4;
    int lrow = tid >> 5;       // 0..7
    int lc4 = (tid & 31) * 4;  // 0..124
    float acc[8][8] = {};

    int nk = (t < 7 ? t : 7) + 1;  // valid lags: k = 0..nk-1
    int C = nk * 32;               // chunks of 8 j-rows

    const float* atb = g_ATs + (size_t)b * (Kk * Nn * Nn);
    const float* hbb = g_h + (size_t)b * (Nn * Tt * Hh);

    // chunk c: k = c>>5, j0 = (c&31)*8
    {
        // prefetch chunk 0
        const float* asrc = atb + (size_t)lrow * Nn + i0 + lc4;           // k=0, j0=0
        const float* hsrc = hbb + ((size_t)lrow * Tt + t) * Hh + n0 + lc4;  // ts=t
        cp_async16(&As[0][lrow][lc4], asrc);
        cp_async16(&Hs[0][lrow][lc4], hsrc);
        asm volatile("cp.async.commit_group;");
    }

    for (int c = 0; c < C; c++) {
        int cur = c & 1;
        if (c + 1 < C) {
            int cn = c + 1;
            int k = cn >> 5;
            int j0 = (cn & 31) * 8;
            const float* asrc =
                atb + (size_t)k * (Nn * Nn) + (size_t)(j0 + lrow) * Nn + i0 + lc4;
            const float* hsrc =
                hbb + ((size_t)(j0 + lrow) * Tt + (t - k)) * Hh + n0 + lc4;
            int nb = cn & 1;
            cp_async16(&As[nb][lrow][lc4], asrc);
            cp_async16(&Hs[nb][lrow][lc4], hsrc);
            asm volatile("cp.async.commit_group;");
            asm volatile("cp.async.wait_group 1;");
        } else {
            asm volatile("cp.async.wait_group 0;");
        }
        __syncthreads();
#pragma unroll
        for (int kk = 0; kk < 8; kk++) {
            float4 a0 = *(const float4*)&As[cur][kk][ty * 8];
            float4 a1 = *(const float4*)&As[cur][kk][ty * 8 + 4];
            float4 b0 = *(const float4*)&Hs[cur][kk][tx * 8];
            float4 b1 = *(const float4*)&Hs[cur][kk][tx * 8 + 4];
            float ar[8] = {a0.x, a0.y, a0.z, a0.w, a1.x, a1.y, a1.z, a1.w};
            float br[8] = {b0.x, b0.y, b0.z, b0.w, b1.x, b1.y, b1.z, b1.w};
#pragma unroll
            for (int i = 0; i < 8; i++)
#pragma unroll
                for (int j = 0; j < 8; j++)
                    acc[i][j] = fmaf(ar[i], br[j], acc[i][j]);
        }
        __syncthreads();
    }

    // store agg[b][t][i][hh]
#pragma unroll
    for (int i = 0; i < 8; i++) {
        int irow = i0 + ty * 8 + i;
        float* outp = g_agg + (((size_t)(b * Tt + t)) * Nn + irow) * Hh + n0 + tx * 8;
        float4 r0 = make_float4(acc[i][0], acc[i][1], acc[i][2], acc[i][3]);
        float4 r1 = make_float4(acc[i][4], acc[i][5], acc[i][6], acc[i][7]);
        *(float4*)outp = r0;
        *(float4*)(outp + 4) = r1;
    }
}

// ---------------------------------------------------------------------------
// K6: res = agg @ out_w + out_b + h_t ; LayerNorm ; gelu ; store transposed.
// Tile 64 rows x 256 cols (full H), warp-per-row LN via shfl.
// ---------------------------------------------------------------------------
__global__ __launch_bounds__(256) void k_out(const float* __restrict__ out_w,
                                             const float* __restrict__ out_b,
                                             const float* __restrict__ ln_g,
                                             const float* __restrict__ ln_b,
                                             float* __restrict__ out) {
    int m0 = blockIdx.x * 64;
    int tid = threadIdx.x;
    int tx = tid & 31, ty = tid >> 5;  // warp ty owns rows ty*8..+7
    __shared__ __align__(16) float As[8][68];
    __shared__ __align__(16) float Bs[8][256];
    float acc[8][8] = {};
    int lrowA = tid >> 2;     // 0..63
    int lk2 = (tid & 3) * 2;  // 0,2,4,6
    int lrowB = tid >> 5;     // 0..7
    int lc8 = (tid & 31) * 8;

    for (int k0 = 0; k0 < Hh; k0 += 8) {
        float2 av = *(const float2*)(g_agg + (size_t)(m0 + lrowA) * Hh + k0 + lk2);
        As[lk2][lrowA] = av.x;
        As[lk2 + 1][lrowA] = av.y;
        *(float4*)&Bs[lrowB][lc8] =
            *(const float4*)(out_w + (size_t)(k0 + lrowB) * Hh + lc8);
        *(float4*)&Bs[lrowB][lc8 + 4] =
            *(const float4*)(out_w + (size_t)(k0 + lrowB) * Hh + lc8 + 4);
        __syncthreads();
#pragma unroll
        for (int kk = 0; kk < 8; kk++) {
            float4 a0 = *(const float4*)&As[kk][ty * 8];
            float4 a1 = *(const float4*)&As[kk][ty * 8 + 4];
            float4 b0 = *(const float4*)&Bs[kk][tx * 8];
            float4 b1 = *(const float4*)&Bs[kk][tx * 8 + 4];
            float ar[8] = {a0.x, a0.y, a0.z, a0.w, a1.x, a1.y, a1.z, a1.w};
            float br[8] = {b0.x, b0.y, b0.z, b0.w, b1.x, b1.y, b1.z, b1.w};
#pragma unroll
            for (int i = 0; i < 8; i++)
#pragma unroll
                for (int j = 0; j < 8; j++) acc[i][j] = fmaf(ar[i], br[j], acc[i][j]);
        }
        __syncthreads();
    }

    // epilogue: bias + residual + LN + gelu, store to out[b][i][t][:]
    float4 ob0 = *(const float4*)(out_b + tx * 8);
    float4 ob1 = *(const float4*)(out_b + tx * 8 + 4);
    float4 lg0 = *(const float4*)(ln_g + tx * 8);
    float4 lg1 = *(const float4*)(ln_g + tx * 8 + 4);
    float4 lb0 = *(const float4*)(ln_b + tx * 8);
    float4 lb1 = *(const float4*)(ln_b + tx * 8 + 4);
    float obr[8] = {ob0.x, ob0.y, ob0.z, ob0.w, ob1.x, ob1.y, ob1.z, ob1.w};
    float lgr[8] = {lg0.x, lg0.y, lg0.z, lg0.w, lg1.x, lg1.y, lg1.z, lg1.w};
    float lbr[8] = {lb0.x, lb0.y, lb0.z, lb0.w, lb1.x, lb1.y, lb1.z, lb1.w};

#pragma unroll
    for (int r = 0; r < 8; r++) {
        int m = m0 + ty * 8 + r;  // row order: [b][t][i]
        int b = m >> 15;
        int t = (m >> 8) & 127;
        int i = m & 255;
        size_t ridx = (((size_t)(b * Nn + i)) * Tt + t) * Hh + tx * 8;
        float4 r0 = *(const float4*)(g_h + ridx);
        float4 r1 = *(const float4*)(g_h + ridx + 4);
        float rr[8] = {r0.x, r0.y, r0.z, r0.w, r1.x, r1.y, r1.z, r1.w};
        float v[8];
        float s = 0.f;
#pragma unroll
        for (int q = 0; q < 8; q++) {
            v[q] = acc[r][q] + obr[q] + rr[q];
            s += v[q];
        }
#pragma unroll
        for (int o = 16; o > 0; o >>= 1) s += __shfl_xor_sync(0xffffffffu, s, o);
        float mu = s * (1.f / 256.f);
        float ss = 0.f;
#pragma unroll
        for (int q = 0; q < 8; q++) {
            float d = v[q] - mu;
            ss += d * d;
        }
#pragma unroll
        for (int o = 16; o > 0; o >>= 1) ss += __shfl_xor_sync(0xffffffffu, ss, o);
        float rstd = rsqrtf(ss * (1.f / 256.f) + 1e-5f);
        float w[8];
#pragma unroll
        for (int q = 0; q < 8; q++)
            w[q] = gelu_exact((v[q] - mu) * rstd * lgr[q] + lbr[q]);
        float4 o0 = make_float4(w[0], w[1], w[2], w[3]);
        float4 o1 = make_float4(w[4], w[5], w[6], w[7]);
        *(float4*)(out + ridx) = o0;
        *(float4*)(out + ridx + 4) = o1;
    }
}

// ---------------------------------------------------------------------------
extern "C" void kernel_launch(void* const* d_in, const int* in_sizes, int n_in,
                              void* d_out, int out_size) {
    (void)in_sizes;
    (void)n_in;
    (void)out_size;
    const float* x = (const float*)d_in[0];
    const float* A_list = (const float*)d_in[1];
    const float* in_w = (const float*)d_in[2];
    const float* in_b = (const float*)d_in[3];
    const float* out_w = (const float*)d_in[4];
    const float* out_b = (const float*)d_in[5];
    const float* lag_embed = (const float*)d_in[6];
    const float* ctx_w1 = (const float*)d_in[7];
    const float* ctx_b1 = (const float*)d_in[8];
    const float* ctx_w2 = (const float*)d_in[9];
    const float* ctx_b2 = (const float*)d_in[10];
    const float* gate_w1 = (const float*)d_in[11];
    const float* gate_b1 = (const float*)d_in[12];
    const float* gate_w2 = (const float*)d_in[13];
    const float* gate_b2 = (const float*)d_in[14];
    const float* ln_g = (const float*)d_in[15];
    const float* ln_b = (const float*)d_in[16];
    float* out = (float*)d_out;

    k_ctx<<<4, 512>>>(x);
    k_alpha<<<1, 32>>>(lag_embed, ctx_w1, ctx_b1, ctx_w2, ctx_b2,
                       gate_w1, gate_b1, gate_w2, gate_b2);
    k_anorm<<<Kk * Nn, Nn>>>(A_list);
    k_ascale<<<(Bq * Kk * Nn * Nn) / 256, 256>>>();
    k_ingemm<<<dim3(2, 1024), 256>>>(x, in_w, in_b);
    k_lag<<<dim3(2, 2, Bq * Tt), 256>>>();
    k_out<<<(Bq * Tt * Nn) / 64, 256>>>(out_w, out_b, ln_g, ln_b, out);
}

// round 4
// speedup vs baseline: 1.0025x; 1.0025x over previous
#include <cuda_runtime.h>
#include <math.h>

#define Bq 4
#define Nn 256
#define Tt 128
#define Fin 64
#define Kk 8
#define Hh 256
#define Ee 8

// Scratch (module-level device globals; no runtime allocation)
__device__ float g_h[Bq * Nn * Tt * Hh];      // [b][j][t][hh]  134 MB
__device__ float g_agg[Bq * Tt * Nn * Hh];    // [b][t][i][hh]  134 MB
__device__ float g_AT[Kk * Nn * Nn];          // [k][j][i] normalized, transposed
__device__ float g_ATs[Bq * Kk * Nn * Nn];    // [b][k][j][i] = alpha[b][k] * g_AT
__device__ float g_ctx[Bq * Fin];
__device__ float g_alpha[Bq * Kk];

__device__ __forceinline__ float gelu_exact(float v) {
    return 0.5f * v * (1.0f + erff(v * 0.7071067811865476f));
}

__device__ __forceinline__ void cp_async16(void* s, const void* g) {
    unsigned saddr = (unsigned)__cvta_generic_to_shared(s);
    asm volatile("cp.async.cg.shared.global [%0], [%1], 16;\n" ::"r"(saddr), "l"(g));
}

// ---------------------------------------------------------------------------
// K1: ctx[b][f] = mean over (N,T) of x
// ---------------------------------------------------------------------------
__global__ void k_ctx(const float* __restrict__ x) {
    int b = blockIdx.x;
    int col = threadIdx.x & 63;
    int g = threadIdx.x >> 6;  // 0..7 (512 threads)
    const float* xb = x + (size_t)b * (Nn * Tt * Fin);
    float acc = 0.f;
    for (int r = g; r < Nn * Tt; r += 8)
        acc += xb[(size_t)r * Fin + col];
    __shared__ float part[8][64];
    part[g][col] = acc;
    __syncthreads();
    if (threadIdx.x < 64) {
        float s = 0.f;
#pragma unroll
        for (int q = 0; q < 8; q++) s += part[q][threadIdx.x];
        g_ctx[b * Fin + threadIdx.x] = s * (1.0f / (Nn * Tt));
    }
}

// ---------------------------------------------------------------------------
// K2: alpha[b][k] = sigmoid(gate MLP([lag_emb[k], ctx_feat[b]]))
// ---------------------------------------------------------------------------
__global__ void k_alpha(const float* __restrict__ lag_embed,
                        const float* __restrict__ ctx_w1, const float* __restrict__ ctx_b1,
                        const float* __restrict__ ctx_w2, const float* __restrict__ ctx_b2,
                        const float* __restrict__ gate_w1, const float* __restrict__ gate_b1,
                        const float* __restrict__ gate_w2, const float* __restrict__ gate_b2) {
    int tid = threadIdx.x;
    if (tid >= Bq * Kk) return;
    int b = tid >> 3, k = tid & 7;
    float t1[Ee];
#pragma unroll
    for (int e = 0; e < Ee; e++) {
        float s = ctx_b1[e];
        for (int f = 0; f < Fin; f++) s += g_ctx[b * Fin + f] * ctx_w1[f * Ee + e];
        t1[e] = gelu_exact(s);
    }
    float cf[Ee];
#pragma unroll
    for (int e = 0; e < Ee; e++) {
        float s = ctx_b2[e];
#pragma unroll
        for (int q = 0; q < Ee; q++) s += t1[q] * ctx_w2[q * Ee + e];
        cf[e] = s;
    }
    float hg[Ee];
#pragma unroll
    for (int e = 0; e < Ee; e++) {
        float s = gate_b1[e];
#pragma unroll
        for (int q = 0; q < Ee; q++) s += lag_embed[k * Ee + q] * gate_w1[q * Ee + e];
#pragma unroll
        for (int q = 0; q < Ee; q++) s += cf[q] * gate_w1[(Ee + q) * Ee + e];
        hg[e] = gelu_exact(s);
    }
    float lg = gate_b2[0];
#pragma unroll
    for (int e = 0; e < Ee; e++) lg += hg[e] * gate_w2[e];
    g_alpha[b * Kk + k] = 1.f / (1.f + expf(-lg));
}

// ---------------------------------------------------------------------------
// K3: row-normalize A and store transposed: g_AT[k][j][i] = A[k][i][j]/rowsum
// ---------------------------------------------------------------------------
__global__ void k_anorm(const float* __restrict__ A) {
    int idx = blockIdx.x;  // k*256 + i
    int j = threadIdx.x;
    float v = A[(size_t)idx * Nn + j];
    __shared__ float red[Nn];
    red[j] = v;
    __syncthreads();
    for (int s = 128; s > 0; s >>= 1) {
        if (j < s) red[j] += red[j + s];
        __syncthreads();
    }
    float inv = 1.f / fmaxf(red[0], 1e-8f);
    int k = idx >> 8, i = idx & 255;
    g_AT[((size_t)(k * Nn + j)) * Nn + i] = v * inv;
}

// ---------------------------------------------------------------------------
// K3b: g_ATs[b][k][j][i] = alpha[b][k] * g_AT[k][j][i]
// ---------------------------------------------------------------------------
__global__ void k_ascale() {
    size_t idx = (size_t)blockIdx.x * blockDim.x + threadIdx.x;  // < 2^21
    int b = (int)(idx >> 19);
    int k = (int)((idx >> 16) & 7);
    g_ATs[idx] = g_alpha[b * Kk + k] * g_AT[idx & ((1u << 19) - 1u)];
}

// ---------------------------------------------------------------------------
// K4: h = x @ in_w + in_b   (M=131072, K=64, N=256) -> g_h (same row order)
// ---------------------------------------------------------------------------
__global__ __launch_bounds__(256) void k_ingemm(const float* __restrict__ x,
                                                const float* __restrict__ in_w,
                                                const float* __restrict__ in_b) {
    __shared__ __align__(16) float As[8][132];
    __shared__ __align__(16) float Bs[8][128];
    int m0 = blockIdx.y * 128;
    int n0 = blockIdx.x * 128;
    int tid = threadIdx.x;
    int tx = tid & 15, ty = tid >> 4;
    int lrowA = tid >> 1;
    int lk4 = (tid & 1) * 4;
    int lrowB = tid >> 5;
    int lc4 = (tid & 31) * 4;
    float acc[8][8] = {};
    for (int k0 = 0; k0 < Fin; k0 += 8) {
        float4 av = *(const float4*)(x + (size_t)(m0 + lrowA) * Fin + k0 + lk4);
        As[lk4 + 0][lrowA] = av.x;
        As[lk4 + 1][lrowA] = av.y;
        As[lk4 + 2][lrowA] = av.z;
        As[lk4 + 3][lrowA] = av.w;
        *(float4*)&Bs[lrowB][lc4] =
            *(const float4*)(in_w + (size_t)(k0 + lrowB) * Hh + n0 + lc4);
        __syncthreads();
#pragma unroll
        for (int kk = 0; kk < 8; kk++) {
            float4 a0 = *(const float4*)&As[kk][ty * 8];
            float4 a1 = *(const float4*)&As[kk][ty * 8 + 4];
            float4 b0 = *(const float4*)&Bs[kk][tx * 8];
            float4 b1 = *(const float4*)&Bs[kk][tx * 8 + 4];
            float ar[8] = {a0.x, a0.y, a0.z, a0.w, a1.x, a1.y, a1.z, a1.w};
            float br[8] = {b0.x, b0.y, b0.z, b0.w, b1.x, b1.y, b1.z, b1.w};
#pragma unroll
            for (int i = 0; i < 8; i++)
#pragma unroll
                for (int j = 0; j < 8; j++) acc[i][j] = fmaf(ar[i], br[j], acc[i][j]);
        }
        __syncthreads();
    }
#pragma unroll
    for (int i = 0; i < 8; i++) {
        int m = m0 + ty * 8 + i;
        float* outp = g_h + (size_t)m * Hh + n0 + tx * 8;
        float4 b0 = *(const float4*)(in_b + n0 + tx * 8);
        float4 b1 = *(const float4*)(in_b + n0 + tx * 8 + 4);
        float4 r0 = make_float4(acc[i][0] + b0.x, acc[i][1] + b0.y,
                                acc[i][2] + b0.z, acc[i][3] + b0.w);
        float4 r1 = make_float4(acc[i][4] + b1.x, acc[i][5] + b1.y,
                                acc[i][6] + b1.z, acc[i][7] + b1.w);
        *(float4*)outp = r0;
        *(float4*)(outp + 4) = r1;
    }
}

// ---------------------------------------------------------------------------
// K5: lag aggregation. Per (b,t):  agg[i,hh] = sum_{k,j} ATs[b][k][j][i]*h[b,j,t-k,hh]
// 128x128 tile, 8x8 micro, cp.async double-buffered over jk chunks of 8.
// ---------------------------------------------------------------------------
__global__ __launch_bounds__(256) void k_lag() {
    int bt = blockIdx.z;
    int b = bt >> 7;
    int t = bt & 127;
    int i0 = blockIdx.y * 128;
    int n0 = blockIdx.x * 128;
    __shared__ __align__(16) float As[2][8][128];
    __shared__ __align__(16) float Hs[2][8][128];
    int tid = threadIdx.x;
    int tx = tid & 15, ty = tid >> 4;
    int lrow = tid >> 5;       // 0..7
    int lc4 = (tid & 31) * 4;  // 0..124
    float acc[8][8] = {};

    int nk = (t < 7 ? t : 7) + 1;  // valid lags: k = 0..nk-1
    int C = nk * 32;               // chunks of 8 j-rows

    const float* atb = g_ATs + (size_t)b * (Kk * Nn * Nn);
    const float* hbb = g_h + (size_t)b * (Nn * Tt * Hh);

    // chunk c: k = c>>5, j0 = (c&31)*8
    {
        // prefetch chunk 0
        const float* asrc = atb + (size_t)lrow * Nn + i0 + lc4;           // k=0, j0=0
        const float* hsrc = hbb + ((size_t)lrow * Tt + t) * Hh + n0 + lc4;  // ts=t
        cp_async16(&As[0][lrow][lc4], asrc);
        cp_async16(&Hs[0][lrow][lc4], hsrc);
        asm volatile("cp.async.commit_group;");
    }

    for (int c = 0; c < C; c++) {
        int cur = c & 1;
        if (c + 1 < C) {
            int cn = c + 1;
            int k = cn >> 5;
            int j0 = (cn & 31) * 8;
            const float* asrc =
                atb + (size_t)k * (Nn * Nn) + (size_t)(j0 + lrow) * Nn + i0 + lc4;
            const float* hsrc =
                hbb + ((size_t)(j0 + lrow) * Tt + (t - k)) * Hh + n0 + lc4;
            int nb = cn & 1;
            cp_async16(&As[nb][lrow][lc4], asrc);
            cp_async16(&Hs[nb][lrow][lc4], hsrc);
            asm volatile("cp.async.commit_group;");
            asm volatile("cp.async.wait_group 1;");
        } else {
            asm volatile("cp.async.wait_group 0;");
        }
        __syncthreads();
#pragma unroll
        for (int kk = 0; kk < 8; kk++) {
            float4 a0 = *(const float4*)&As[cur][kk][ty * 8];
            float4 a1 = *(const float4*)&As[cur][kk][ty * 8 + 4];
            float4 b0 = *(const float4*)&Hs[cur][kk][tx * 8];
            float4 b1 = *(const float4*)&Hs[cur][kk][tx * 8 + 4];
            float ar[8] = {a0.x, a0.y, a0.z, a0.w, a1.x, a1.y, a1.z, a1.w};
            float br[8] = {b0.x, b0.y, b0.z, b0.w, b1.x, b1.y, b1.z, b1.w};
#pragma unroll
            for (int i = 0; i < 8; i++)
#pragma unroll
                for (int j = 0; j < 8; j++)
                    acc[i][j] = fmaf(ar[i], br[j], acc[i][j]);
        }
        __syncthreads();
    }

    // store agg[b][t][i][hh]
#pragma unroll
    for (int i = 0; i < 8; i++) {
        int irow = i0 + ty * 8 + i;
        float* outp = g_agg + (((size_t)(b * Tt + t)) * Nn + irow) * Hh + n0 + tx * 8;
        float4 r0 = make_float4(acc[i][0], acc[i][1], acc[i][2], acc[i][3]);
        float4 r1 = make_float4(acc[i][4], acc[i][5], acc[i][6], acc[i][7]);
        *(float4*)outp = r0;
        *(float4*)(outp + 4) = r1;
    }
}

// ---------------------------------------------------------------------------
// K6: res = agg @ out_w + out_b + h_t ; LayerNorm ; gelu ; store transposed.
// Tile 64 rows x 256 cols (full H), warp-per-row LN via shfl.
// ---------------------------------------------------------------------------
__global__ __launch_bounds__(256) void k_out(const float* __restrict__ out_w,
                                             const float* __restrict__ out_b,
                                             const float* __restrict__ ln_g,
                                             const float* __restrict__ ln_b,
                                             float* __restrict__ out) {
    int m0 = blockIdx.x * 64;
    int tid = threadIdx.x;
    int tx = tid & 31, ty = tid >> 5;  // warp ty owns rows ty*8..+7
    __shared__ __align__(16) float As[8][68];
    __shared__ __align__(16) float Bs[8][256];
    float acc[8][8] = {};
    int lrowA = tid >> 2;     // 0..63
    int lk2 = (tid & 3) * 2;  // 0,2,4,6
    int lrowB = tid >> 5;     // 0..7
    int lc8 = (tid & 31) * 8;

    for (int k0 = 0; k0 < Hh; k0 += 8) {
        float2 av = *(const float2*)(g_agg + (size_t)(m0 + lrowA) * Hh + k0 + lk2);
        As[lk2][lrowA] = av.x;
        As[lk2 + 1][lrowA] = av.y;
        *(float4*)&Bs[lrowB][lc8] =
            *(const float4*)(out_w + (size_t)(k0 + lrowB) * Hh + lc8);
        *(float4*)&Bs[lrowB][lc8 + 4] =
            *(const float4*)(out_w + (size_t)(k0 + lrowB) * Hh + lc8 + 4);
        __syncthreads();
#pragma unroll
        for (int kk = 0; kk < 8; kk++) {
            float4 a0 = *(const float4*)&As[kk][ty * 8];
            float4 a1 = *(const float4*)&As[kk][ty * 8 + 4];
            float4 b0 = *(const float4*)&Bs[kk][tx * 8];
            float4 b1 = *(const float4*)&Bs[kk][tx * 8 + 4];
            float ar[8] = {a0.x, a0.y, a0.z, a0.w, a1.x, a1.y, a1.z, a1.w};
            float br[8] = {b0.x, b0.y, b0.z, b0.w, b1.x, b1.y, b1.z, b1.w};
#pragma unroll
            for (int i = 0; i < 8; i++)
#pragma unroll
                for (int j = 0; j < 8; j++) acc[i][j] = fmaf(ar[i], br[j], acc[i][j]);
        }
        __syncthreads();
    }

    // epilogue: bias + residual + LN + gelu, store to out[b][i][t][:]
    float4 ob0 = *(const float4*)(out_b + tx * 8);
    float4 ob1 = *(const float4*)(out_b + tx * 8 + 4);
    float4 lg0 = *(const float4*)(ln_g + tx * 8);
    float4 lg1 = *(const float4*)(ln_g + tx * 8 + 4);
    float4 lb0 = *(const float4*)(ln_b + tx * 8);
    float4 lb1 = *(const float4*)(ln_b + tx * 8 + 4);
    float obr[8] = {ob0.x, ob0.y, ob0.z, ob0.w, ob1.x, ob1.y, ob1.z, ob1.w};
    float lgr[8] = {lg0.x, lg0.y, lg0.z, lg0.w, lg1.x, lg1.y, lg1.z, lg1.w};
    float lbr[8] = {lb0.x, lb0.y, lb0.z, lb0.w, lb1.x, lb1.y, lb1.z, lb1.w};

#pragma unroll
    for (int r = 0; r < 8; r++) {
        int m = m0 + ty * 8 + r;  // row order: [b][t][i]
        int b = m >> 15;
        int t = (m >> 8) & 127;
        int i = m & 255;
        size_t ridx = (((size_t)(b * Nn + i)) * Tt + t) * Hh + tx * 8;
        float4 r0 = *(const float4*)(g_h + ridx);
        float4 r1 = *(const float4*)(g_h + ridx + 4);
        float rr[8] = {r0.x, r0.y, r0.z, r0.w, r1.x, r1.y, r1.z, r1.w};
        float v[8];
        float s = 0.f;
#pragma unroll
        for (int q = 0; q < 8; q++) {
            v[q] = acc[r][q] + obr[q] + rr[q];
            s += v[q];
        }
#pragma unroll
        for (int o = 16; o > 0; o >>= 1) s += __shfl_xor_sync(0xffffffffu, s, o);
        float mu = s * (1.f / 256.f);
        float ss = 0.f;
#pragma unroll
        for (int q = 0; q < 8; q++) {
            float d = v[q] - mu;
            ss += d * d;
        }
#pragma unroll
        for (int o = 16; o > 0; o >>= 1) ss += __shfl_xor_sync(0xffffffffu, ss, o);
        float rstd = rsqrtf(ss * (1.f / 256.f) + 1e-5f);
        float w[8];
#pragma unroll
        for (int q = 0; q < 8; q++)
            w[q] = gelu_exact((v[q] - mu) * rstd * lgr[q] + lbr[q]);
        float4 o0 = make_float4(w[0], w[1], w[2], w[3]);
        float4 o1 = make_float4(w[4], w[5], w[6], w[7]);
        *(float4*)(out + ridx) = o0;
        *(float4*)(out + ridx + 4) = o1;
    }
}

// ---------------------------------------------------------------------------
extern "C" void kernel_launch(void* const* d_in, const int* in_sizes, int n_in,
                              void* d_out, int out_size) {
    (void)in_sizes;
    (void)n_in;
    (void)out_size;
    const float* x = (const float*)d_in[0];
    const float* A_list = (const float*)d_in[1];
    const float* in_w = (const float*)d_in[2];
    const float* in_b = (const float*)d_in[3];
    const float* out_w = (const float*)d_in[4];
    const float* out_b = (const float*)d_in[5];
    const float* lag_embed = (const float*)d_in[6];
    const float* ctx_w1 = (const float*)d_in[7];
    const float* ctx_b1 = (const float*)d_in[8];
    const float* ctx_w2 = (const float*)d_in[9];
    const float* ctx_b2 = (const float*)d_in[10];
    const float* gate_w1 = (const float*)d_in[11];
    const float* gate_b1 = (const float*)d_in[12];
    const float* gate_w2 = (const float*)d_in[13];
    const float* gate_b2 = (const float*)d_in[14];
    const float* ln_g = (const float*)d_in[15];
    const float* ln_b = (const float*)d_in[16];
    float* out = (float*)d_out;

    k_ctx<<<4, 512>>>(x);
    k_alpha<<<1, 32>>>(lag_embed, ctx_w1, ctx_b1, ctx_w2, ctx_b2,
                       gate_w1, gate_b1, gate_w2, gate_b2);
    k_anorm<<<Kk * Nn, Nn>>>(A_list);
    k_ascale<<<(Bq * Kk * Nn * Nn) / 256, 256>>>();
    k_ingemm<<<dim3(2, 1024), 256>>>(x, in_w, in_b);
    k_lag<<<dim3(2, 2, Bq * Tt), 256>>>();
    k_out<<<(Bq * Tt * Nn) / 64, 256>>>(out_w, out_b, ln_g, ln_b, out);
}

// round 7
// speedup vs baseline: 1.6628x; 1.6586x over previous
#include <cuda_runtime.h>
#include <cuda_bf16.h>
#include <math.h>
#include <stdint.h>

#define Bq 4
#define Nn 256
#define Tt 128
#define Fin 64
#define Kk 8
#define Hh 256
#define Ee 8

// ---------------- device scratch (no runtime allocation) -------------------
__device__ float g_h[(size_t)Bq * Nn * Tt * Hh];    // [b][j][t][hh] 134MB
__device__ float g_agg[(size_t)Bq * Tt * Nn * Hh];  // [b][t][i][hh] 134MB
__device__ float g_An[Kk * Nn * Nn];                // [k][i][j] row-normalized
__device__ float g_ctx[Bq * Fin];
__device__ float g_alpha[Bq * Kk];
// packed bf16 operands: A' = alpha*A_norm transposed -> [b][k][pl][j][i]
__device__ __align__(256) __nv_bfloat16 g_Apk[(size_t)Bq * Kk * 2 * Nn * Nn];  // 17MB
// H' = h transposed slices -> [b][t][pl][j][hh]
__device__ __align__(256) __nv_bfloat16 g_Hpk[(size_t)Bq * Tt * 2 * Nn * Hh];  // 134MB

// ---------------- helpers ---------------------------------------------------
__device__ __forceinline__ uint32_t smem_u32(const void* p) {
    uint32_t a;
    asm("{ .reg .u64 t; cvta.to.shared.u64 t, %1; cvt.u32.u64 %0, t; }" : "=r"(a) : "l"(p));
    return a;
}
__device__ __forceinline__ void cp_async16(void* s, const void* g) {
    unsigned saddr = smem_u32(s);
    asm volatile("cp.async.cg.shared.global [%0], [%1], 16;\n" ::"r"(saddr), "l"(g));
}
__device__ __forceinline__ float gelu_exact(float v) {
    return 0.5f * v * (1.0f + erff(v * 0.7071067811865476f));
}
#define LDSM_T(r0, r1, r2, r3, addr)                                                   \
    asm volatile("ldmatrix.sync.aligned.m8n8.x4.trans.shared.b16 {%0,%1,%2,%3}, [%4];" \
                 : "=r"(r0), "=r"(r1), "=r"(r2), "=r"(r3) : "r"(addr))
__device__ __forceinline__ void mma_bf16(float* c, const uint32_t* a, const uint32_t* b) {
    asm volatile(
        "mma.sync.aligned.m16n8k16.row.col.f32.bf16.bf16.f32 "
        "{%0,%1,%2,%3}, {%4,%5,%6,%7}, {%8,%9}, {%0,%1,%2,%3};"
        : "+f"(c[0]), "+f"(c[1]), "+f"(c[2]), "+f"(c[3])
        : "r"(a[0]), "r"(a[1]), "r"(a[2]), "r"(a[3]), "r"(b[0]), "r"(b[1]));
}

// ---------------------------------------------------------------------------
__global__ void k_ctx(const float* __restrict__ x) {
    int b = blockIdx.x;
    int col = threadIdx.x & 63;
    int g = threadIdx.x >> 6;
    const float* xb = x + (size_t)b * (Nn * Tt * Fin);
    float acc = 0.f;
    for (int r = g; r < Nn * Tt; r += 8) acc += xb[(size_t)r * Fin + col];
    __shared__ float part[8][64];
    part[g][col] = acc;
    __syncthreads();
    if (threadIdx.x < 64) {
        float s = 0.f;
#pragma unroll
        for (int q = 0; q < 8; q++) s += part[q][threadIdx.x];
        g_ctx[b * Fin + threadIdx.x] = s * (1.0f / (Nn * Tt));
    }
}

__global__ void k_alpha(const float* __restrict__ lag_embed,
                        const float* __restrict__ ctx_w1, const float* __restrict__ ctx_b1,
                        const float* __restrict__ ctx_w2, const float* __restrict__ ctx_b2,
                        const float* __restrict__ gate_w1, const float* __restrict__ gate_b1,
                        const float* __restrict__ gate_w2, const float* __restrict__ gate_b2) {
    int tid = threadIdx.x;
    if (tid >= Bq * Kk) return;
    int b = tid >> 3, k = tid & 7;
    float t1[Ee];
#pragma unroll
    for (int e = 0; e < Ee; e++) {
        float s = ctx_b1[e];
        for (int f = 0; f < Fin; f++) s += g_ctx[b * Fin + f] * ctx_w1[f * Ee + e];
        t1[e] = gelu_exact(s);
    }
    float cf[Ee];
#pragma unroll
    for (int e = 0; e < Ee; e++) {
        float s = ctx_b2[e];
#pragma unroll
        for (int q = 0; q < Ee; q++) s += t1[q] * ctx_w2[q * Ee + e];
        cf[e] = s;
    }
    float hg[Ee];
#pragma unroll
    for (int e = 0; e < Ee; e++) {
        float s = gate_b1[e];
#pragma unroll
        for (int q = 0; q < Ee; q++) s += lag_embed[k * Ee + q] * gate_w1[q * Ee + e];
#pragma unroll
        for (int q = 0; q < Ee; q++) s += cf[q] * gate_w1[(Ee + q) * Ee + e];
        hg[e] = gelu_exact(s);
    }
    float lg = gate_b2[0];
#pragma unroll
    for (int e = 0; e < Ee; e++) lg += hg[e] * gate_w2[e];
    g_alpha[b * Kk + k] = 1.f / (1.f + expf(-lg));
}

__global__ void k_anorm(const float* __restrict__ A) {
    int idx = blockIdx.x;  // k*256+i
    int j = threadIdx.x;
    float v = A[(size_t)idx * Nn + j];
    __shared__ float red[Nn];
    red[j] = v;
    __syncthreads();
    for (int s = 128; s > 0; s >>= 1) {
        if (j < s) red[j] += red[j + s];
        __syncthreads();
    }
    g_An[(size_t)idx * Nn + j] = v * (1.f / fmaxf(red[0], 1e-8f));
}

// h = x @ in_w + in_b ; ALSO emit packed bf16 hi/lo transposed H' in the epilogue
__global__ __launch_bounds__(256) void k_ingemm(const float* __restrict__ x,
                                                const float* __restrict__ in_w,
                                                const float* __restrict__ in_b) {
    __shared__ __align__(16) float As[8][132];
    __shared__ __align__(16) float Bs[8][128];
    int m0 = blockIdx.y * 128;
    int n0 = blockIdx.x * 128;
    int tid = threadIdx.x;
    int tx = tid & 15, ty = tid >> 4;
    int lrowA = tid >> 1;
    int lk4 = (tid & 1) * 4;
    int lrowB = tid >> 5;
    int lc4 = (tid & 31) * 4;
    float acc[8][8] = {};
    for (int k0 = 0; k0 < Fin; k0 += 8) {
        float4 av = *(const float4*)(x + (size_t)(m0 + lrowA) * Fin + k0 + lk4);
        As[lk4 + 0][lrowA] = av.x;
        As[lk4 + 1][lrowA] = av.y;
        As[lk4 + 2][lrowA] = av.z;
        As[lk4 + 3][lrowA] = av.w;
        *(float4*)&Bs[lrowB][lc4] = *(const float4*)(in_w + (size_t)(k0 + lrowB) * Hh + n0 + lc4);
        __syncthreads();
#pragma unroll
        for (int kk = 0; kk < 8; kk++) {
            float4 a0 = *(const float4*)&As[kk][ty * 8];
            float4 a1 = *(const float4*)&As[kk][ty * 8 + 4];
            float4 b0 = *(const float4*)&Bs[kk][tx * 8];
            float4 b1 = *(const float4*)&Bs[kk][tx * 8 + 4];
            float ar[8] = {a0.x, a0.y, a0.z, a0.w, a1.x, a1.y, a1.z, a1.w};
            float br[8] = {b0.x, b0.y, b0.z, b0.w, b1.x, b1.y, b1.z, b1.w};
#pragma unroll
            for (int i = 0; i < 8; i++)
#pragma unroll
                for (int j = 0; j < 8; j++) acc[i][j] = fmaf(ar[i], br[j], acc[i][j]);
        }
        __syncthreads();
    }
    float4 bb0 = *(const float4*)(in_b + n0 + tx * 8);
    float4 bb1 = *(const float4*)(in_b + n0 + tx * 8 + 4);
    float bias[8] = {bb0.x, bb0.y, bb0.z, bb0.w, bb1.x, bb1.y, bb1.z, bb1.w};
#pragma unroll
    for (int i = 0; i < 8; i++) {
        int m = m0 + ty * 8 + i;
        float v[8];
#pragma unroll
        for (int q = 0; q < 8; q++) v[q] = acc[i][q] + bias[q];
        float* outp = g_h + (size_t)m * Hh + n0 + tx * 8;
        *(float4*)outp = make_float4(v[0], v[1], v[2], v[3]);
        *(float4*)(outp + 4) = make_float4(v[4], v[5], v[6], v[7]);
        // packed transposed: row m = b*32768 + j*128 + t ; cols hh = n0+tx*8..+7
        int b = m >> 15, j = (m >> 7) & 255, t = m & 127;
        __nv_bfloat16* hip = g_Hpk + ((size_t)(b * Tt + t) * 2) * 65536 + j * 256 + n0 + tx * 8;
        __nv_bfloat16* lop = hip + 65536;
        __nv_bfloat16 hv[8], lv[8];
#pragma unroll
        for (int q = 0; q < 8; q++) {
            hv[q] = __float2bfloat16(v[q]);
            lv[q] = __float2bfloat16(v[q] - __bfloat162float(hv[q]));
        }
        *(float4*)hip = *(float4*)hv;
        *(float4*)lop = *(float4*)lv;
    }
}

// pack alpha*An transposed: g_Apk[b][k][pl][j][i]
__global__ __launch_bounds__(256) void k_packA() {
    int b = blockIdx.x >> 3, k = blockIdx.x & 7;
    float al = g_alpha[b * 8 + k];
    __shared__ float sm[32][33];
    const float* an = g_An + (size_t)k * 65536;
    __nv_bfloat16* hip = g_Apk + ((size_t)(b * 8 + k) * 2) * 65536;
    __nv_bfloat16* lop = hip + 65536;
    int r8 = threadIdx.x >> 5, c = threadIdx.x & 31;
    for (int ti = 0; ti < 8; ti++)
        for (int tj = 0; tj < 8; tj++) {
            int i0 = ti * 32, j0 = tj * 32;
            __syncthreads();
#pragma unroll
            for (int q = 0; q < 4; q++) {
                int r = r8 + q * 8;
                sm[r][c] = an[(size_t)(i0 + r) * 256 + j0 + c];
            }
            __syncthreads();
#pragma unroll
            for (int q = 0; q < 4; q++) {
                int r = r8 + q * 8;
                float v = al * sm[c][r];
                __nv_bfloat16 h = __float2bfloat16(v);
                float lo = v - __bfloat162float(h);
                hip[(size_t)(j0 + r) * 256 + i0 + c] = h;
                lop[(size_t)(j0 + r) * 256 + i0 + c] = __float2bfloat16(lo);
            }
        }
}

// ---------------------------------------------------------------------------
// k_lagmma: C[i0+128, n0+128] per (b,t) via mma.sync bf16 hi/lo (3 MMAs)
// ---------------------------------------------------------------------------
__global__ __launch_bounds__(256, 1) void k_lagmma() {
    __shared__ __align__(16) __nv_bfloat16 As[2][2][16][136];
    __shared__ __align__(16) __nv_bfloat16 Hs[2][2][16][136];
    int tid = threadIdx.x, lane = tid & 31, wid = tid >> 5;
    int n0 = blockIdx.x * 128, i0 = blockIdx.y * 128;
    int bt = blockIdx.z;
    int b = bt >> 7, t = bt & 127;
    int nk = (t < 7 ? t : 7) + 1;
    int C = nk * 16;  // chunks of 16 j
    int wm = wid & 3, wn = wid >> 2;
    int m0w = wm * 32, n0w = wn * 64;
    float cacc[2][8][4];
#pragma unroll
    for (int a = 0; a < 2; a++)
#pragma unroll
        for (int bb = 0; bb < 8; bb++)
#pragma unroll
            for (int q = 0; q < 4; q++) cacc[a][bb][q] = 0.f;

    int crow = tid >> 4, cseg = tid & 15;
    const __nv_bfloat16* Ab = g_Apk + ((size_t)(b * 8) * 2) * 65536;
    const __nv_bfloat16* Hb = g_Hpk + ((size_t)(b * 128) * 2) * 65536;

    auto issue = [&](int cc, int buf) {
        int k = cc >> 4, j0 = (cc & 15) * 16, ts = t - k;
        const __nv_bfloat16* ap =
            Ab + ((size_t)k * 2) * 65536 + (size_t)(j0 + crow) * 256 + i0 + cseg * 8;
        const __nv_bfloat16* hp =
            Hb + ((size_t)ts * 2) * 65536 + (size_t)(j0 + crow) * 256 + n0 + cseg * 8;
        cp_async16(&As[buf][0][crow][cseg * 8], ap);
        cp_async16(&As[buf][1][crow][cseg * 8], ap + 65536);
        cp_async16(&Hs[buf][0][crow][cseg * 8], hp);
        cp_async16(&Hs[buf][1][crow][cseg * 8], hp + 65536);
        asm volatile("cp.async.commit_group;");
    };
    issue(0, 0);

    int krA = (lane & 7) + ((lane >> 4) << 3);
    int mcA = m0w + (lane & 8);
    int krB = (lane & 7) + (lane & 8);
    int ncB = n0w + ((lane >> 4) << 3);

    for (int cc = 0; cc < C; cc++) {
        int buf = cc & 1;
        if (cc + 1 < C) {
            issue(cc + 1, (cc + 1) & 1);
            asm volatile("cp.async.wait_group 1;");
        } else {
            asm volatile("cp.async.wait_group 0;");
        }
        __syncthreads();

        uint32_t Af[2][2][4];  // [pl][mt][4]
#pragma unroll
        for (int pl = 0; pl < 2; pl++)
#pragma unroll
            for (int mt = 0; mt < 2; mt++) {
                uint32_t ad = smem_u32(&As[buf][pl][krA][mcA + mt * 16]);
                LDSM_T(Af[pl][mt][0], Af[pl][mt][1], Af[pl][mt][2], Af[pl][mt][3], ad);
            }
        uint32_t Bf[2][8][2];  // [pl][nt][2]
#pragma unroll
        for (int pl = 0; pl < 2; pl++)
#pragma unroll
            for (int p = 0; p < 4; p++) {
                uint32_t r0, r1, r2, r3;
                uint32_t bd = smem_u32(&Hs[buf][pl][krB][ncB + p * 16]);
                LDSM_T(r0, r1, r2, r3, bd);
                Bf[pl][2 * p][0] = r0;
                Bf[pl][2 * p][1] = r1;
                Bf[pl][2 * p + 1][0] = r2;
                Bf[pl][2 * p + 1][1] = r3;
            }
#pragma unroll
        for (int mt = 0; mt < 2; mt++)
#pragma unroll
            for (int nt = 0; nt < 8; nt++) {
                mma_bf16(cacc[mt][nt], Af[0][mt], Bf[0][nt]);
                mma_bf16(cacc[mt][nt], Af[0][mt], Bf[1][nt]);
                mma_bf16(cacc[mt][nt], Af[1][mt], Bf[0][nt]);
            }
        __syncthreads();
    }

    // store C -> g_agg[b][t][i][hh]
    int rbase = i0 + m0w + (lane >> 2);
    int cbase = n0 + n0w + (lane & 3) * 2;
    float* ob = g_agg + (size_t)bt * Nn * Hh;
#pragma unroll
    for (int mt = 0; mt < 2; mt++)
#pragma unroll
        for (int nt = 0; nt < 8; nt++) {
            int r = rbase + mt * 16;
            int cl = cbase + nt * 8;
            *(float2*)(ob + (size_t)r * Hh + cl) = make_float2(cacc[mt][nt][0], cacc[mt][nt][1]);
            *(float2*)(ob + (size_t)(r + 8) * Hh + cl) = make_float2(cacc[mt][nt][2], cacc[mt][nt][3]);
        }
}

// ---------------------------------------------------------------------------
// K6: res = agg @ out_w + out_b + h_t ; LayerNorm ; gelu ; transposed store
// ---------------------------------------------------------------------------
__global__ __launch_bounds__(256) void k_out(const float* __restrict__ out_w,
                                             const float* __restrict__ out_b,
                                             const float* __restrict__ ln_g,
                                             const float* __restrict__ ln_b,
                                             float* __restrict__ out) {
    int m0 = blockIdx.x * 64;
    int tid = threadIdx.x;
    int tx = tid & 31, ty = tid >> 5;
    __shared__ __align__(16) float As[8][68];
    __shared__ __align__(16) float Bs[8][256];
    float acc[8][8] = {};
    int lrowA = tid >> 2;
    int lk2 = (tid & 3) * 2;
    int lrowB = tid >> 5;
    int lc8 = (tid & 31) * 8;

    for (int k0 = 0; k0 < Hh; k0 += 8) {
        float2 av = *(const float2*)(g_agg + (size_t)(m0 + lrowA) * Hh + k0 + lk2);
        As[lk2][lrowA] = av.x;
        As[lk2 + 1][lrowA] = av.y;
        *(float4*)&Bs[lrowB][lc8] = *(const float4*)(out_w + (size_t)(k0 + lrowB) * Hh + lc8);
        *(float4*)&Bs[lrowB][lc8 + 4] = *(const float4*)(out_w + (size_t)(k0 + lrowB) * Hh + lc8 + 4);
        __syncthreads();
#pragma unroll
        for (int kk = 0; kk < 8; kk++) {
            float4 a0 = *(const float4*)&As[kk][ty * 8];
            float4 a1 = *(const float4*)&As[kk][ty * 8 + 4];
            float4 b0 = *(const float4*)&Bs[kk][tx * 8];
            float4 b1 = *(const float4*)&Bs[kk][tx * 8 + 4];
            float ar[8] = {a0.x, a0.y, a0.z, a0.w, a1.x, a1.y, a1.z, a1.w};
            float br[8] = {b0.x, b0.y, b0.z, b0.w, b1.x, b1.y, b1.z, b1.w};
#pragma unroll
            for (int i = 0; i < 8; i++)
#pragma unroll
                for (int j = 0; j < 8; j++) acc[i][j] = fmaf(ar[i], br[j], acc[i][j]);
        }
        __syncthreads();
    }

    float4 ob0 = *(const float4*)(out_b + tx * 8);
    float4 ob1 = *(const float4*)(out_b + tx * 8 + 4);
    float4 lg0 = *(const float4*)(ln_g + tx * 8);
    float4 lg1 = *(const float4*)(ln_g + tx * 8 + 4);
    float4 lb0 = *(const float4*)(ln_b + tx * 8);
    float4 lb1 = *(const float4*)(ln_b + tx * 8 + 4);
    float obr[8] = {ob0.x, ob0.y, ob0.z, ob0.w, ob1.x, ob1.y, ob1.z, ob1.w};
    float lgr[8] = {lg0.x, lg0.y, lg0.z, lg0.w, lg1.x, lg1.y, lg1.z, lg1.w};
    float lbr[8] = {lb0.x, lb0.y, lb0.z, lb0.w, lb1.x, lb1.y, lb1.z, lb1.w};

#pragma unroll
    for (int r = 0; r < 8; r++) {
        int m = m0 + ty * 8 + r;
        int b = m >> 15;
        int t = (m >> 8) & 127;
        int i = m & 255;
        size_t ridx = (((size_t)(b * Nn + i)) * Tt + t) * Hh + tx * 8;
        float4 r0 = *(const float4*)(g_h + ridx);
        float4 r1 = *(const float4*)(g_h + ridx + 4);
        float rr[8] = {r0.x, r0.y, r0.z, r0.w, r1.x, r1.y, r1.z, r1.w};
        float v[8];
        float s = 0.f;
#pragma unroll
        for (int q = 0; q < 8; q++) {
            v[q] = acc[r][q] + obr[q] + rr[q];
            s += v[q];
        }
#pragma unroll
        for (int o = 16; o > 0; o >>= 1) s += __shfl_xor_sync(0xffffffffu, s, o);
        float mu = s * (1.f / 256.f);
        float ss = 0.f;
#pragma unroll
        for (int q = 0; q < 8; q++) {
            float d = v[q] - mu;
            ss += d * d;
        }
#pragma unroll
        for (int o = 16; o > 0; o >>= 1) ss += __shfl_xor_sync(0xffffffffu, ss, o);
        float rstd = rsqrtf(ss * (1.f / 256.f) + 1e-5f);
        float w[8];
#pragma unroll
        for (int q = 0; q < 8; q++) w[q] = gelu_exact((v[q] - mu) * rstd * lgr[q] + lbr[q]);
        *(float4*)(out + ridx) = make_float4(w[0], w[1], w[2], w[3]);
        *(float4*)(out + ridx + 4) = make_float4(w[4], w[5], w[6], w[7]);
    }
}

// ---------------------------------------------------------------------------
extern "C" void kernel_launch(void* const* d_in, const int* in_sizes, int n_in,
                              void* d_out, int out_size) {
    (void)in_sizes;
    (void)n_in;
    (void)out_size;
    const float* x = (const float*)d_in[0];
    const float* A_list = (const float*)d_in[1];
    const float* in_w = (const float*)d_in[2];
    const float* in_b = (const float*)d_in[3];
    const float* out_w = (const float*)d_in[4];
    const float* out_b = (const float*)d_in[5];
    const float* lag_embed = (const float*)d_in[6];
    const float* ctx_w1 = (const float*)d_in[7];
    const float* ctx_b1 = (const float*)d_in[8];
    const float* ctx_w2 = (const float*)d_in[9];
    const float* ctx_b2 = (const float*)d_in[10];
    const float* gate_w1 = (const float*)d_in[11];
    const float* gate_b1 = (const float*)d_in[12];
    const float* gate_w2 = (const float*)d_in[13];
    const float* gate_b2 = (const float*)d_in[14];
    const float* ln_g = (const float*)d_in[15];
    const float* ln_b = (const float*)d_in[16];
    float* out = (float*)d_out;

    k_ctx<<<4, 512>>>(x);
    k_alpha<<<1, 32>>>(lag_embed, ctx_w1, ctx_b1, ctx_w2, ctx_b2,
                       gate_w1, gate_b1, gate_w2, gate_b2);
    k_anorm<<<Kk * Nn, Nn>>>(A_list);
    k_ingemm<<<dim3(2, 1024), 256>>>(x, in_w, in_b);
    k_packA<<<Bq * Kk, 256>>>();
    k_lagmma<<<dim3(2, 2, Bq * Tt), 256>>>();
    k_out<<<(Bq * Tt * Nn) / 64, 256>>>(out_w, out_b, ln_g, ln_b, out);
}

// round 9
// speedup vs baseline: 2.1071x; 1.2673x over previous
#include <cuda_runtime.h>
#include <cuda_bf16.h>
#include <math.h>
#include <stdint.h>

#define Bq 4
#define Nn 256
#define Tt 128
#define Fin 64
#define Kk 8
#define Hh 256
#define Ee 8

// ---------------- device scratch (no runtime allocation) -------------------
__device__ float g_An[Kk * Nn * Nn];  // [k][i][j] row-normalized
__device__ float g_ctx[Bq * Fin];
__device__ float g_alpha[Bq * Kk];
// packed bf16 operands: A' = alpha*A_norm transposed -> [b][k][pl][j][i]
__device__ __align__(256) __nv_bfloat16 g_Apk[(size_t)Bq * Kk * 2 * Nn * Nn];  // 17MB
// H' = h transposed slices -> [b][t][pl][j][hh]   (also the LN residual source)
__device__ __align__(256) __nv_bfloat16 g_Hpk[(size_t)Bq * Tt * 2 * Nn * Hh];  // 134MB
// agg packed -> [b*t][pl][i][hh]
__device__ __align__(256) __nv_bfloat16 g_aggpk[(size_t)Bq * Tt * 2 * Nn * Hh];  // 134MB
// out_w packed -> [pl][hh][c]
__device__ __align__(256) __nv_bfloat16 g_Wpk[2 * Hh * Hh];

// ---------------- helpers ---------------------------------------------------
__device__ __forceinline__ uint32_t smem_u32(const void* p) {
    uint32_t a;
    asm("{ .reg .u64 t; cvta.to.shared.u64 t, %1; cvt.u32.u64 %0, t; }" : "=r"(a) : "l"(p));
    return a;
}
__device__ __forceinline__ void cp_async16(void* s, const void* g) {
    unsigned saddr = smem_u32(s);
    asm volatile("cp.async.cg.shared.global [%0], [%1], 16;\n" ::"r"(saddr), "l"(g));
}
__device__ __forceinline__ float gelu_exact(float v) {
    return 0.5f * v * (1.0f + erff(v * 0.7071067811865476f));
}
#define LDSM_T(r0, r1, r2, r3, addr)                                                   \
    asm volatile("ldmatrix.sync.aligned.m8n8.x4.trans.shared.b16 {%0,%1,%2,%3}, [%4];" \
                 : "=r"(r0), "=r"(r1), "=r"(r2), "=r"(r3) : "r"(addr))
#define LDSM_N(r0, r1, r2, r3, addr)                                                   \
    asm volatile("ldmatrix.sync.aligned.m8n8.x4.shared.b16 {%0,%1,%2,%3}, [%4];"       \
                 : "=r"(r0), "=r"(r1), "=r"(r2), "=r"(r3) : "r"(addr))
__device__ __forceinline__ void mma_bf16(float* c, const uint32_t* a, const uint32_t* b) {
    asm volatile(
        "mma.sync.aligned.m16n8k16.row.col.f32.bf16.bf16.f32 "
        "{%0,%1,%2,%3}, {%4,%5,%6,%7}, {%8,%9}, {%0,%1,%2,%3};"
        : "+f"(c[0]), "+f"(c[1]), "+f"(c[2]), "+f"(c[3])
        : "r"(a[0]), "r"(a[1]), "r"(a[2]), "r"(a[3]), "r"(b[0]), "r"(b[1]));
}

// ---------------------------------------------------------------------------
__global__ void k_ctx(const float* __restrict__ x) {
    int b = blockIdx.x;
    int col = threadIdx.x & 63;
    int g = threadIdx.x >> 6;
    const float* xb = x + (size_t)b * (Nn * Tt * Fin);
    float acc = 0.f;
    for (int r = g; r < Nn * Tt; r += 8) acc += xb[(size_t)r * Fin + col];
    __shared__ float part[8][64];
    part[g][col] = acc;
    __syncthreads();
    if (threadIdx.x < 64) {
        float s = 0.f;
#pragma unroll
        for (int q = 0; q < 8; q++) s += part[q][threadIdx.x];
        g_ctx[b * Fin + threadIdx.x] = s * (1.0f / (Nn * Tt));
    }
}

__global__ void k_alpha(const float* __restrict__ lag_embed,
                        const float* __restrict__ ctx_w1, const float* __restrict__ ctx_b1,
                        const float* __restrict__ ctx_w2, const float* __restrict__ ctx_b2,
                        const float* __restrict__ gate_w1, const float* __restrict__ gate_b1,
                        const float* __restrict__ gate_w2, const float* __restrict__ gate_b2) {
    int tid = threadIdx.x;
    if (tid >= Bq * Kk) return;
    int b = tid >> 3, k = tid & 7;
    float t1[Ee];
#pragma unroll
    for (int e = 0; e < Ee; e++) {
        float s = ctx_b1[e];
        for (int f = 0; f < Fin; f++) s += g_ctx[b * Fin + f] * ctx_w1[f * Ee + e];
        t1[e] = gelu_exact(s);
    }
    float cf[Ee];
#pragma unroll
    for (int e = 0; e < Ee; e++) {
        float s = ctx_b2[e];
#pragma unroll
        for (int q = 0; q < Ee; q++) s += t1[q] * ctx_w2[q * Ee + e];
        cf[e] = s;
    }
    float hg[Ee];
#pragma unroll
    for (int e = 0; e < Ee; e++) {
        float s = gate_b1[e];
#pragma unroll
        for (int q = 0; q < Ee; q++) s += lag_embed[k * Ee + q] * gate_w1[q * Ee + e];
#pragma unroll
        for (int q = 0; q < Ee; q++) s += cf[q] * gate_w1[(Ee + q) * Ee + e];
        hg[e] = gelu_exact(s);
    }
    float lg = gate_b2[0];
#pragma unroll
    for (int e = 0; e < Ee; e++) lg += hg[e] * gate_w2[e];
    g_alpha[b * Kk + k] = 1.f / (1.f + expf(-lg));
}

__global__ void k_anorm(const float* __restrict__ A) {
    int idx = blockIdx.x;  // k*256+i
    int j = threadIdx.x;
    float v = A[(size_t)idx * Nn + j];
    __shared__ float red[Nn];
    red[j] = v;
    __syncthreads();
    for (int s = 128; s > 0; s >>= 1) {
        if (j < s) red[j] += red[j + s];
        __syncthreads();
    }
    g_An[(size_t)idx * Nn + j] = v * (1.f / fmaxf(red[0], 1e-8f));
}

// pack out_w -> g_Wpk[pl][hh][c]
__global__ void k_packW(const float* __restrict__ out_w) {
    int hh = blockIdx.x, c = threadIdx.x;
    float v = out_w[hh * Hh + c];
    __nv_bfloat16 h = __float2bfloat16(v);
    g_Wpk[hh * Hh + c] = h;
    g_Wpk[65536 + hh * Hh + c] = __float2bfloat16(v - __bfloat162float(h));
}

// h = x @ in_w + in_b, emitted ONLY as packed bf16 hi/lo transposed H'
__global__ __launch_bounds__(256) void k_ingemm(const float* __restrict__ x,
                                                const float* __restrict__ in_w,
                                                const float* __restrict__ in_b) {
    __shared__ __align__(16) float As[8][132];
    __shared__ __align__(16) float Bs[8][128];
    int m0 = blockIdx.y * 128;
    int n0 = blockIdx.x * 128;
    int tid = threadIdx.x;
    int tx = tid & 15, ty = tid >> 4;
    int lrowA = tid >> 1;
    int lk4 = (tid & 1) * 4;
    int lrowB = tid >> 5;
    int lc4 = (tid & 31) * 4;
    float acc[8][8] = {};
    for (int k0 = 0; k0 < Fin; k0 += 8) {
        float4 av = *(const float4*)(x + (size_t)(m0 + lrowA) * Fin + k0 + lk4);
        As[lk4 + 0][lrowA] = av.x;
        As[lk4 + 1][lrowA] = av.y;
        As[lk4 + 2][lrowA] = av.z;
        As[lk4 + 3][lrowA] = av.w;
        *(float4*)&Bs[lrowB][lc4] = *(const float4*)(in_w + (size_t)(k0 + lrowB) * Hh + n0 + lc4);
        __syncthreads();
#pragma unroll
        for (int kk = 0; kk < 8; kk++) {
            float4 a0 = *(const float4*)&As[kk][ty * 8];
            float4 a1 = *(const float4*)&As[kk][ty * 8 + 4];
            float4 b0 = *(const float4*)&Bs[kk][tx * 8];
            float4 b1 = *(const float4*)&Bs[kk][tx * 8 + 4];
            float ar[8] = {a0.x, a0.y, a0.z, a0.w, a1.x, a1.y, a1.z, a1.w};
            float br[8] = {b0.x, b0.y, b0.z, b0.w, b1.x, b1.y, b1.z, b1.w};
#pragma unroll
            for (int i = 0; i < 8; i++)
#pragma unroll
                for (int j = 0; j < 8; j++) acc[i][j] = fmaf(ar[i], br[j], acc[i][j]);
        }
        __syncthreads();
    }
    float4 bb0 = *(const float4*)(in_b + n0 + tx * 8);
    float4 bb1 = *(const float4*)(in_b + n0 + tx * 8 + 4);
    float bias[8] = {bb0.x, bb0.y, bb0.z, bb0.w, bb1.x, bb1.y, bb1.z, bb1.w};
#pragma unroll
    for (int i = 0; i < 8; i++) {
        int m = m0 + ty * 8 + i;
        float v[8];
#pragma unroll
        for (int q = 0; q < 8; q++) v[q] = acc[i][q] + bias[q];
        // packed transposed: row m = b*32768 + j*128 + t ; cols hh = n0+tx*8..+7
        int b = m >> 15, j = (m >> 7) & 255, t = m & 127;
        __nv_bfloat16* hip = g_Hpk + ((size_t)(b * Tt + t) * 2) * 65536 + j * 256 + n0 + tx * 8;
        __nv_bfloat16* lop = hip + 65536;
        __nv_bfloat16 hv[8], lv[8];
#pragma unroll
        for (int q = 0; q < 8; q++) {
            hv[q] = __float2bfloat16(v[q]);
            lv[q] = __float2bfloat16(v[q] - __bfloat162float(hv[q]));
        }
        *(float4*)hip = *(float4*)hv;
        *(float4*)lop = *(float4*)lv;
    }
}

// pack alpha*An transposed: g_Apk[b][k][pl][j][i]
__global__ __launch_bounds__(256) void k_packA() {
    int b = blockIdx.x >> 3, k = blockIdx.x & 7;
    float al = g_alpha[b * 8 + k];
    __shared__ float sm[32][33];
    const float* an = g_An + (size_t)k * 65536;
    __nv_bfloat16* hip = g_Apk + ((size_t)(b * 8 + k) * 2) * 65536;
    __nv_bfloat16* lop = hip + 65536;
    int r8 = threadIdx.x >> 5, c = threadIdx.x & 31;
    for (int ti = 0; ti < 8; ti++)
        for (int tj = 0; tj < 8; tj++) {
            int i0 = ti * 32, j0 = tj * 32;
            __syncthreads();
#pragma unroll
            for (int q = 0; q < 4; q++) {
                int r = r8 + q * 8;
                sm[r][c] = an[(size_t)(i0 + r) * 256 + j0 + c];
            }
            __syncthreads();
#pragma unroll
            for (int q = 0; q < 4; q++) {
                int r = r8 + q * 8;
                float v = al * sm[c][r];
                __nv_bfloat16 h = __float2bfloat16(v);
                float lo = v - __bfloat162float(h);
                hip[(size_t)(j0 + r) * 256 + i0 + c] = h;
                lop[(size_t)(j0 + r) * 256 + i0 + c] = __float2bfloat16(lo);
            }
        }
}

// ---------------------------------------------------------------------------
// k_lagmma: C[i0+128, n0+128] per (b,t) via mma.sync bf16 hi/lo (3 MMAs)
// epilogue emits packed bf16 hi/lo agg (row-major [i][hh])
// ---------------------------------------------------------------------------
__global__ __launch_bounds__(256, 2) void k_lagmma() {
    __shared__ __align__(16) __nv_bfloat16 As[2][2][16][136];
    __shared__ __align__(16) __nv_bfloat16 Hs[2][2][16][136];
    int tid = threadIdx.x, lane = tid & 31, wid = tid >> 5;
    int n0 = blockIdx.x * 128, i0 = blockIdx.y * 128;
    int bt = blockIdx.z;
    int b = bt >> 7, t = bt & 127;
    int nk = (t < 7 ? t : 7) + 1;
    int C = nk * 16;  // chunks of 16 j
    int wm = wid & 3, wn = wid >> 2;
    int m0w = wm * 32, n0w = wn * 64;
    float cacc[2][8][4];
#pragma unroll
    for (int a = 0; a < 2; a++)
#pragma unroll
        for (int bb = 0; bb < 8; bb++)
#pragma unroll
            for (int q = 0; q < 4; q++) cacc[a][bb][q] = 0.f;

    int crow = tid >> 4, cseg = tid & 15;
    const __nv_bfloat16* Ab = g_Apk + ((size_t)(b * 8) * 2) * 65536;
    const __nv_bfloat16* Hb = g_Hpk + ((size_t)(b * 128) * 2) * 65536;

    auto issue = [&](int cc, int buf) {
        int k = cc >> 4, j0 = (cc & 15) * 16, ts = t - k;
        const __nv_bfloat16* ap =
            Ab + ((size_t)k * 2) * 65536 + (size_t)(j0 + crow) * 256 + i0 + cseg * 8;
        const __nv_bfloat16* hp =
            Hb + ((size_t)ts * 2) * 65536 + (size_t)(j0 + crow) * 256 + n0 + cseg * 8;
        cp_async16(&As[buf][0][crow][cseg * 8], ap);
        cp_async16(&As[buf][1][crow][cseg * 8], ap + 65536);
        cp_async16(&Hs[buf][0][crow][cseg * 8], hp);
        cp_async16(&Hs[buf][1][crow][cseg * 8], hp + 65536);
        asm volatile("cp.async.commit_group;");
    };
    issue(0, 0);

    int krA = (lane & 7) + ((lane >> 4) << 3);
    int mcA = m0w + (lane & 8);
    int krB = (lane & 7) + (lane & 8);
    int ncB = n0w + ((lane >> 4) << 3);

    for (int cc = 0; cc < C; cc++) {
        int buf = cc & 1;
        if (cc + 1 < C) {
            issue(cc + 1, (cc + 1) & 1);
            asm volatile("cp.async.wait_group 1;");
        } else {
            asm volatile("cp.async.wait_group 0;");
        }
        __syncthreads();

        uint32_t Af[2][2][4];  // [pl][mt][4]
#pragma unroll
        for (int pl = 0; pl < 2; pl++)
#pragma unroll
            for (int mt = 0; mt < 2; mt++) {
                uint32_t ad = smem_u32(&As[buf][pl][krA][mcA + mt * 16]);
                LDSM_T(Af[pl][mt][0], Af[pl][mt][1], Af[pl][mt][2], Af[pl][mt][3], ad);
            }
        uint32_t Bf[8][2];  // one plane at a time (register diet)
#pragma unroll
        for (int p = 0; p < 4; p++) {
            uint32_t r0, r1, r2, r3;
            uint32_t bd = smem_u32(&Hs[buf][0][krB][ncB + p * 16]);
            LDSM_T(r0, r1, r2, r3, bd);
            Bf[2 * p][0] = r0;
            Bf[2 * p][1] = r1;
            Bf[2 * p + 1][0] = r2;
            Bf[2 * p + 1][1] = r3;
        }
#pragma unroll
        for (int mt = 0; mt < 2; mt++)
#pragma unroll
            for (int nt = 0; nt < 8; nt++) {
                mma_bf16(cacc[mt][nt], Af[0][mt], Bf[nt]);  // Ah*Bh
                mma_bf16(cacc[mt][nt], Af[1][mt], Bf[nt]);  // Al*Bh
            }
#pragma unroll
        for (int p = 0; p < 4; p++) {
            uint32_t r0, r1, r2, r3;
            uint32_t bd = smem_u32(&Hs[buf][1][krB][ncB + p * 16]);
            LDSM_T(r0, r1, r2, r3, bd);
            Bf[2 * p][0] = r0;
            Bf[2 * p][1] = r1;
            Bf[2 * p + 1][0] = r2;
            Bf[2 * p + 1][1] = r3;
        }
#pragma unroll
        for (int mt = 0; mt < 2; mt++)
#pragma unroll
            for (int nt = 0; nt < 8; nt++) mma_bf16(cacc[mt][nt], Af[0][mt], Bf[nt]);  // Ah*Bl
        __syncthreads();
    }

    // store packed agg hi/lo: g_aggpk[bt][pl][i][hh]
    int rbase = i0 + m0w + (lane >> 2);
    int cbase = n0 + n0w + (lane & 3) * 2;
    __nv_bfloat16* hipl = g_aggpk + ((size_t)bt * 2) * 65536;
    __nv_bfloat16* lopl = hipl + 65536;
#pragma unroll
    for (int mt = 0; mt < 2; mt++)
#pragma unroll
        for (int nt = 0; nt < 8; nt++) {
            int r = rbase + mt * 16;
            int cl = cbase + nt * 8;
#pragma unroll
            for (int s = 0; s < 2; s++) {
                float v0 = cacc[mt][nt][s * 2], v1 = cacc[mt][nt][s * 2 + 1];
                __nv_bfloat162 h2 = __floats2bfloat162_rn(v0, v1);
                __nv_bfloat162 l2 = __floats2bfloat162_rn(v0 - __bfloat162float(h2.x),
                                                          v1 - __bfloat162float(h2.y));
                size_t off = (size_t)(r + s * 8) * 256 + cl;
                *(__nv_bfloat162*)(hipl + off) = h2;
                *(__nv_bfloat162*)(lopl + off) = l2;
            }
        }
}

// ---------------------------------------------------------------------------
// k_outmma: res = agg @ out_w + out_b + h_t ; LN ; gelu ; transposed store
// block = 64 rows (m = bt*256 + i), 256 cols. tensor-core 3-term bf16.
// ---------------------------------------------------------------------------
__global__ __launch_bounds__(256, 2) void k_outmma(const float* __restrict__ out_b,
                                                   const float* __restrict__ ln_g,
                                                   const float* __restrict__ ln_b,
                                                   float* __restrict__ out) {
    __shared__ __align__(16) __nv_bfloat16 As[2][2][64][24];   // agg tile [row][k16] pad24
    __shared__ __align__(16) __nv_bfloat16 Bs[2][2][16][264];  // W tile [k][col] pad264
    __shared__ float redS[64][4][2];
    int tid = threadIdx.x, lane = tid & 31, wid = tid >> 5;
    int m0 = blockIdx.x * 64;
    int bt = m0 >> 8;
    int i0 = m0 & 255;
    int b = bt >> 7, t = bt & 127;
    int wm = wid & 1, wn = wid >> 1;  // 2 m-warps x 4 n-warps
    int m0w = wm * 32, n0w = wn * 64;
    float cacc[2][8][4];
#pragma unroll
    for (int a = 0; a < 2; a++)
#pragma unroll
        for (int bb = 0; bb < 8; bb++)
#pragma unroll
            for (int q = 0; q < 4; q++) cacc[a][bb][q] = 0.f;

    const __nv_bfloat16* Agg = g_aggpk + ((size_t)bt * 2) * 65536;

    // A: pl = tid>>7, row = (tid>>1)&63, seg = tid&1 (one cp.async each)
    int aPl = tid >> 7, aRow = (tid >> 1) & 63, aSeg = tid & 1;
    auto issue = [&](int cc, int buf) {
        int k0 = cc * 16;
        cp_async16(&As[buf][aPl][aRow][aSeg * 8],
                   Agg + (size_t)aPl * 65536 + (size_t)(i0 + aRow) * 256 + k0 + aSeg * 8);
#pragma unroll
        for (int q = 0; q < 4; q++) {
            int idx = tid + q * 256;
            int pl = idx >> 9, krow = (idx >> 5) & 15, seg = idx & 31;
            cp_async16(&Bs[buf][pl][krow][seg * 8],
                       g_Wpk + pl * 65536 + (size_t)(k0 + krow) * 256 + seg * 8);
        }
        asm volatile("cp.async.commit_group;");
    };
    issue(0, 0);

    int mrA = (lane & 15);
    int kcA = (lane >> 4) * 8;
    int krB = (lane & 7) + (lane & 8);
    int ncB = n0w + ((lane >> 4) << 3);

    for (int cc = 0; cc < 16; cc++) {
        int buf = cc & 1;
        if (cc + 1 < 16) {
            issue(cc + 1, (cc + 1) & 1);
            asm volatile("cp.async.wait_group 1;");
        } else {
            asm volatile("cp.async.wait_group 0;");
        }
        __syncthreads();

        uint32_t Af[2][2][4];  // [pl][mt][4]  (non-trans: A row-major [m][k])
#pragma unroll
        for (int pl = 0; pl < 2; pl++)
#pragma unroll
            for (int mt = 0; mt < 2; mt++) {
                uint32_t ad = smem_u32(&As[buf][pl][m0w + mt * 16 + mrA][kcA]);
                LDSM_N(Af[pl][mt][0], Af[pl][mt][1], Af[pl][mt][2], Af[pl][mt][3], ad);
            }
        uint32_t Bf[8][2];
#pragma unroll
        for (int p = 0; p < 4; p++) {
            uint32_t r0, r1, r2, r3;
            uint32_t bd = smem_u32(&Bs[buf][0][krB][ncB + p * 16]);
            LDSM_T(r0, r1, r2, r3, bd);
            Bf[2 * p][0] = r0;
            Bf[2 * p][1] = r1;
            Bf[2 * p + 1][0] = r2;
            Bf[2 * p + 1][1] = r3;
        }
#pragma unroll
        for (int mt = 0; mt < 2; mt++)
#pragma unroll
            for (int nt = 0; nt < 8; nt++) {
                mma_bf16(cacc[mt][nt], Af[0][mt], Bf[nt]);
                mma_bf16(cacc[mt][nt], Af[1][mt], Bf[nt]);
            }
#pragma unroll
        for (int p = 0; p < 4; p++) {
            uint32_t r0, r1, r2, r3;
            uint32_t bd = smem_u32(&Bs[buf][1][krB][ncB + p * 16]);
            LDSM_T(r0, r1, r2, r3, bd);
            Bf[2 * p][0] = r0;
            Bf[2 * p][1] = r1;
            Bf[2 * p + 1][0] = r2;
            Bf[2 * p + 1][1] = r3;
        }
#pragma unroll
        for (int mt = 0; mt < 2; mt++)
#pragma unroll
            for (int nt = 0; nt < 8; nt++) mma_bf16(cacc[mt][nt], Af[0][mt], Bf[nt]);
        __syncthreads();
    }

    // ---- epilogue: bias + residual(from Hpk hi+lo) + LN + gelu + store ----
    const __nv_bfloat16* Rh = g_Hpk + ((size_t)(b * Tt + t) * 2) * 65536;
    const __nv_bfloat16* Rl = Rh + 65536;
    float obr[16], lgr[16], lbr[16];
#pragma unroll
    for (int nt = 0; nt < 8; nt++) {
        int c = n0w + nt * 8 + (lane & 3) * 2;
        obr[nt * 2] = out_b[c];
        obr[nt * 2 + 1] = out_b[c + 1];
        lgr[nt * 2] = ln_g[c];
        lgr[nt * 2 + 1] = ln_g[c + 1];
        lbr[nt * 2] = ln_b[c];
        lbr[nt * 2 + 1] = ln_b[c + 1];
    }
    float vv[2][8][4];
    float rsum[4] = {}, rsq[4] = {};
#pragma unroll
    for (int mt = 0; mt < 2; mt++)
#pragma unroll
        for (int s = 0; s < 2; s++) {
            int rloc = m0w + mt * 16 + s * 8 + (lane >> 2);
            int i = i0 + rloc;
#pragma unroll
            for (int nt = 0; nt < 8; nt++) {
                int c = n0w + nt * 8 + (lane & 3) * 2;
                size_t off = (size_t)i * 256 + c;
                __nv_bfloat162 rh = *(const __nv_bfloat162*)(Rh + off);
                __nv_bfloat162 rl = *(const __nv_bfloat162*)(Rl + off);
                float v0 = cacc[mt][nt][s * 2] + obr[nt * 2] +
                           __bfloat162float(rh.x) + __bfloat162float(rl.x);
                float v1 = cacc[mt][nt][s * 2 + 1] + obr[nt * 2 + 1] +
                           __bfloat162float(rh.y) + __bfloat162float(rl.y);
                vv[mt][nt][s * 2] = v0;
                vv[mt][nt][s * 2 + 1] = v1;
                int ri = mt * 2 + s;
                rsum[ri] += v0 + v1;
                rsq[ri] += v0 * v0 + v1 * v1;
            }
        }
#pragma unroll
    for (int ri = 0; ri < 4; ri++) {
#pragma unroll
        for (int o = 1; o < 4; o <<= 1) {
            rsum[ri] += __shfl_xor_sync(0xffffffffu, rsum[ri], o);
            rsq[ri] += __shfl_xor_sync(0xffffffffu, rsq[ri], o);
        }
    }
    if ((lane & 3) == 0) {
#pragma unroll
        for (int mt = 0; mt < 2; mt++)
#pragma unroll
            for (int s = 0; s < 2; s++) {
                int rloc = m0w + mt * 16 + s * 8 + (lane >> 2);
                redS[rloc][wn][0] = rsum[mt * 2 + s];
                redS[rloc][wn][1] = rsq[mt * 2 + s];
            }
    }
    __syncthreads();
#pragma unroll
    for (int mt = 0; mt < 2; mt++)
#pragma unroll
        for (int s = 0; s < 2; s++) {
            int rloc = m0w + mt * 16 + s * 8 + (lane >> 2);
            int i = i0 + rloc;
            float su = redS[rloc][0][0] + redS[rloc][1][0] + redS[rloc][2][0] + redS[rloc][3][0];
            float sq = redS[rloc][0][1] + redS[rloc][1][1] + redS[rloc][2][1] + redS[rloc][3][1];
            float mu = su * (1.f / 256.f);
            float var = sq * (1.f / 256.f) - mu * mu;
            float rstd = rsqrtf(var + 1e-5f);
            float* ob = out + (((size_t)(b * Nn + i)) * Tt + t) * Hh;
#pragma unroll
            for (int nt = 0; nt < 8; nt++) {
                int c = n0w + nt * 8 + (lane & 3) * 2;
                float w0 = gelu_exact((vv[mt][nt][s * 2] - mu) * rstd * lgr[nt * 2] + lbr[nt * 2]);
                float w1 = gelu_exact((vv[mt][nt][s * 2 + 1] - mu) * rstd * lgr[nt * 2 + 1] +
                                      lbr[nt * 2 + 1]);
                *(float2*)(ob + c) = make_float2(w0, w1);
            }
        }
}

// ---------------------------------------------------------------------------
extern "C" void kernel_launch(void* const* d_in, const int* in_sizes, int n_in,
                              void* d_out, int out_size) {
    (void)in_sizes;
    (void)n_in;
    (void)out_size;
    const float* x = (const float*)d_in[0];
    const float* A_list = (const float*)d_in[1];
    const float* in_w = (const float*)d_in[2];
    const float* in_b = (const float*)d_in[3];
    const float* out_w = (const float*)d_in[4];
    const float* out_b = (const float*)d_in[5];
    const float* lag_embed = (const float*)d_in[6];
    const float* ctx_w1 = (const float*)d_in[7];
    const float* ctx_b1 = (const float*)d_in[8];
    const float* ctx_w2 = (const float*)d_in[9];
    const float* ctx_b2 = (const float*)d_in[10];
    const float* gate_w1 = (const float*)d_in[11];
    const float* gate_b1 = (const float*)d_in[12];
    const float* gate_w2 = (const float*)d_in[13];
    const float* gate_b2 = (const float*)d_in[14];
    const float* ln_g = (const float*)d_in[15];
    const float* ln_b = (const float*)d_in[16];
    float* out = (float*)d_out;

    k_ctx<<<4, 512>>>(x);
    k_alpha<<<1, 32>>>(lag_embed, ctx_w1, ctx_b1, ctx_w2, ctx_b2,
                       gate_w1, gate_b1, gate_w2, gate_b2);
    k_anorm<<<Kk * Nn, Nn>>>(A_list);
    k_packW<<<Hh, Hh>>>(out_w);
    k_ingemm<<<dim3(2, 1024), 256>>>(x, in_w, in_b);
    k_packA<<<Bq * Kk, 256>>>();
    k_lagmma<<<dim3(2, 2, Bq * Tt), 256>>>();
    k_outmma<<<(Bq * Tt * Nn) / 64, 256>>>(out_b, ln_g, ln_b, out);
}

// round 10
// speedup vs baseline: 2.4561x; 1.1656x over previous
#include <cuda_runtime.h>
#include <cuda_bf16.h>
#include <math.h>
#include <stdint.h>

#define Bq 4
#define Nn 256
#define Tt 128
#define Fin 64
#define Kk 8
#define Hh 256
#define Ee 8

// ---------------- device scratch (no runtime allocation) -------------------
__device__ float g_An[Kk * Nn * Nn];  // [k][i][j] row-normalized
__device__ float g_ctx[Bq * Fin];
// packed bf16 operands: A' = alpha*A_norm transposed -> [b][k][pl][j][i]
__device__ __align__(256) __nv_bfloat16 g_Apk[(size_t)Bq * Kk * 2 * Nn * Nn];  // 17MB
// H' = h transposed slices -> [b][t][pl][j][hh]   (also the LN residual source)
__device__ __align__(256) __nv_bfloat16 g_Hpk[(size_t)Bq * Tt * 2 * Nn * Hh];  // 134MB
// agg packed -> [b*t][pl][i][hh]
__device__ __align__(256) __nv_bfloat16 g_aggpk[(size_t)Bq * Tt * 2 * Nn * Hh];  // 134MB
// out_w packed -> [pl][hh][c]
__device__ __align__(256) __nv_bfloat16 g_Wpk[2 * Hh * Hh];

// ---------------- helpers ---------------------------------------------------
__device__ __forceinline__ uint32_t smem_u32(const void* p) {
    uint32_t a;
    asm("{ .reg .u64 t; cvta.to.shared.u64 t, %1; cvt.u32.u64 %0, t; }" : "=r"(a) : "l"(p));
    return a;
}
__device__ __forceinline__ void cp_async16(void* s, const void* g) {
    unsigned saddr = smem_u32(s);
    asm volatile("cp.async.cg.shared.global [%0], [%1], 16;\n" ::"r"(saddr), "l"(g));
}
__device__ __forceinline__ float gelu_exact(float v) {
    return 0.5f * v * (1.0f + erff(v * 0.7071067811865476f));
}
#define LDSM_T(r0, r1, r2, r3, addr)                                                   \
    asm volatile("ldmatrix.sync.aligned.m8n8.x4.trans.shared.b16 {%0,%1,%2,%3}, [%4];" \
                 : "=r"(r0), "=r"(r1), "=r"(r2), "=r"(r3) : "r"(addr))
#define LDSM_N(r0, r1, r2, r3, addr)                                                   \
    asm volatile("ldmatrix.sync.aligned.m8n8.x4.shared.b16 {%0,%1,%2,%3}, [%4];"       \
                 : "=r"(r0), "=r"(r1), "=r"(r2), "=r"(r3) : "r"(addr))
__device__ __forceinline__ void mma_bf16(float* c, const uint32_t* a, const uint32_t* b) {
    asm volatile(
        "mma.sync.aligned.m16n8k16.row.col.f32.bf16.bf16.f32 "
        "{%0,%1,%2,%3}, {%4,%5,%6,%7}, {%8,%9}, {%0,%1,%2,%3};"
        : "+f"(c[0]), "+f"(c[1]), "+f"(c[2]), "+f"(c[3])
        : "r"(a[0]), "r"(a[1]), "r"(a[2]), "r"(a[3]), "r"(b[0]), "r"(b[1]));
}

// ---------------------------------------------------------------------------
// k_ctxanorm: blocks 0..3 -> ctx mean; blocks 4..1027 -> A row-normalize (2 rows each)
// ---------------------------------------------------------------------------
__global__ __launch_bounds__(512) void k_ctxanorm(const float* __restrict__ x,
                                                  const float* __restrict__ A) {
    if (blockIdx.x < 4) {
        int b = blockIdx.x;
        int col = threadIdx.x & 63;
        int g = threadIdx.x >> 6;
        const float* xb = x + (size_t)b * (Nn * Tt * Fin);
        float acc = 0.f;
        for (int r = g; r < Nn * Tt; r += 8) acc += xb[(size_t)r * Fin + col];
        __shared__ float part[8][64];
        part[g][col] = acc;
        __syncthreads();
        if (threadIdx.x < 64) {
            float s = 0.f;
#pragma unroll
            for (int q = 0; q < 8; q++) s += part[q][threadIdx.x];
            g_ctx[b * Fin + threadIdx.x] = s * (1.0f / (Nn * Tt));
        }
    } else {
        __shared__ float red[2][256];
        int half = threadIdx.x >> 8;  // 0/1
        int j = threadIdx.x & 255;
        int row = (blockIdx.x - 4) * 2 + half;  // k*256+i
        float v = A[(size_t)row * Nn + j];
        red[half][j] = v;
        __syncthreads();
        for (int s = 128; s > 0; s >>= 1) {
            if (j < s) red[half][j] += red[half][j + s];
            __syncthreads();
        }
        g_An[(size_t)row * Nn + j] = v * (1.f / fmaxf(red[half][0], 1e-8f));
    }
}

// h = x @ in_w + in_b, emitted ONLY as packed bf16 hi/lo transposed H'
__global__ __launch_bounds__(256) void k_ingemm(const float* __restrict__ x,
                                                const float* __restrict__ in_w,
                                                const float* __restrict__ in_b) {
    __shared__ __align__(16) float As[8][132];
    __shared__ __align__(16) float Bs[8][128];
    int m0 = blockIdx.y * 128;
    int n0 = blockIdx.x * 128;
    int tid = threadIdx.x;
    int tx = tid & 15, ty = tid >> 4;
    int lrowA = tid >> 1;
    int lk4 = (tid & 1) * 4;
    int lrowB = tid >> 5;
    int lc4 = (tid & 31) * 4;
    float acc[8][8] = {};
    for (int k0 = 0; k0 < Fin; k0 += 8) {
        float4 av = *(const float4*)(x + (size_t)(m0 + lrowA) * Fin + k0 + lk4);
        As[lk4 + 0][lrowA] = av.x;
        As[lk4 + 1][lrowA] = av.y;
        As[lk4 + 2][lrowA] = av.z;
        As[lk4 + 3][lrowA] = av.w;
        *(float4*)&Bs[lrowB][lc4] = *(const float4*)(in_w + (size_t)(k0 + lrowB) * Hh + n0 + lc4);
        __syncthreads();
#pragma unroll
        for (int kk = 0; kk < 8; kk++) {
            float4 a0 = *(const float4*)&As[kk][ty * 8];
            float4 a1 = *(const float4*)&As[kk][ty * 8 + 4];
            float4 b0 = *(const float4*)&Bs[kk][tx * 8];
            float4 b1 = *(const float4*)&Bs[kk][tx * 8 + 4];
            float ar[8] = {a0.x, a0.y, a0.z, a0.w, a1.x, a1.y, a1.z, a1.w};
            float br[8] = {b0.x, b0.y, b0.z, b0.w, b1.x, b1.y, b1.z, b1.w};
#pragma unroll
            for (int i = 0; i < 8; i++)
#pragma unroll
                for (int j = 0; j < 8; j++) acc[i][j] = fmaf(ar[i], br[j], acc[i][j]);
        }
        __syncthreads();
    }
    float4 bb0 = *(const float4*)(in_b + n0 + tx * 8);
    float4 bb1 = *(const float4*)(in_b + n0 + tx * 8 + 4);
    float bias[8] = {bb0.x, bb0.y, bb0.z, bb0.w, bb1.x, bb1.y, bb1.z, bb1.w};
#pragma unroll
    for (int i = 0; i < 8; i++) {
        int m = m0 + ty * 8 + i;
        float v[8];
#pragma unroll
        for (int q = 0; q < 8; q++) v[q] = acc[i][q] + bias[q];
        // packed transposed: row m = b*32768 + j*128 + t ; cols hh = n0+tx*8..+7
        int b = m >> 15, j = (m >> 7) & 255, t = m & 127;
        __nv_bfloat16* hip = g_Hpk + ((size_t)(b * Tt + t) * 2) * 65536 + j * 256 + n0 + tx * 8;
        __nv_bfloat16* lop = hip + 65536;
        __nv_bfloat16 hv[8], lv[8];
#pragma unroll
        for (int q = 0; q < 8; q++) {
            hv[q] = __float2bfloat16(v[q]);
            lv[q] = __float2bfloat16(v[q] - __bfloat162float(hv[q]));
        }
        *(float4*)hip = *(float4*)hv;
        *(float4*)lop = *(float4*)lv;
    }
}

// pack alpha*An transposed: g_Apk[b][k][pl][j][i]; alpha computed inline (1 thread)
__global__ __launch_bounds__(256) void k_packA(const float* __restrict__ lag_embed,
                                               const float* __restrict__ ctx_w1,
                                               const float* __restrict__ ctx_b1,
                                               const float* __restrict__ ctx_w2,
                                               const float* __restrict__ ctx_b2,
                                               const float* __restrict__ gate_w1,
                                               const float* __restrict__ gate_b1,
                                               const float* __restrict__ gate_w2,
                                               const float* __restrict__ gate_b2) {
    int b = blockIdx.x >> 3, k = blockIdx.x & 7;
    __shared__ float s_alpha;
    if (threadIdx.x == 0) {
        float t1[Ee];
#pragma unroll
        for (int e = 0; e < Ee; e++) {
            float s = ctx_b1[e];
            for (int f = 0; f < Fin; f++) s += g_ctx[b * Fin + f] * ctx_w1[f * Ee + e];
            t1[e] = gelu_exact(s);
        }
        float cf[Ee];
#pragma unroll
        for (int e = 0; e < Ee; e++) {
            float s = ctx_b2[e];
#pragma unroll
            for (int q = 0; q < Ee; q++) s += t1[q] * ctx_w2[q * Ee + e];
            cf[e] = s;
        }
        float hg[Ee];
#pragma unroll
        for (int e = 0; e < Ee; e++) {
            float s = gate_b1[e];
#pragma unroll
            for (int q = 0; q < Ee; q++) s += lag_embed[k * Ee + q] * gate_w1[q * Ee + e];
#pragma unroll
            for (int q = 0; q < Ee; q++) s += cf[q] * gate_w1[(Ee + q) * Ee + e];
            hg[e] = gelu_exact(s);
        }
        float lg = gate_b2[0];
#pragma unroll
        for (int e = 0; e < Ee; e++) lg += hg[e] * gate_w2[e];
        s_alpha = 1.f / (1.f + expf(-lg));
    }
    __syncthreads();
    float al = s_alpha;

    __shared__ float sm[32][33];
    const float* an = g_An + (size_t)k * 65536;
    __nv_bfloat16* hip = g_Apk + ((size_t)(b * 8 + k) * 2) * 65536;
    __nv_bfloat16* lop = hip + 65536;
    int r8 = threadIdx.x >> 5, c = threadIdx.x & 31;
    for (int ti = 0; ti < 8; ti++)
        for (int tj = 0; tj < 8; tj++) {
            int i0 = ti * 32, j0 = tj * 32;
            __syncthreads();
#pragma unroll
            for (int q = 0; q < 4; q++) {
                int r = r8 + q * 8;
                sm[r][c] = an[(size_t)(i0 + r) * 256 + j0 + c];
            }
            __syncthreads();
#pragma unroll
            for (int q = 0; q < 4; q++) {
                int r = r8 + q * 8;
                float v = al * sm[c][r];
                __nv_bfloat16 h = __float2bfloat16(v);
                float lo = v - __bfloat162float(h);
                hip[(size_t)(j0 + r) * 256 + i0 + c] = h;
                lop[(size_t)(j0 + r) * 256 + i0 + c] = __float2bfloat16(lo);
            }
        }
}

// pack out_w -> g_Wpk[pl][hh][c]
__global__ void k_packW(const float* __restrict__ out_w) {
    int hh = blockIdx.x, c = threadIdx.x;
    float v = out_w[hh * Hh + c];
    __nv_bfloat16 h = __float2bfloat16(v);
    g_Wpk[hh * Hh + c] = h;
    g_Wpk[65536 + hh * Hh + c] = __float2bfloat16(v - __bfloat162float(h));
}

// ---------------------------------------------------------------------------
// k_lagmma: C[i0+128, n0+128] per (b,t) via mma.sync bf16 hi/lo (3 MMAs)
// single __syncthreads per chunk (issue-after-barrier multistage pattern)
// ---------------------------------------------------------------------------
__global__ __launch_bounds__(256, 2) void k_lagmma() {
    __shared__ __align__(16) __nv_bfloat16 As[2][2][16][136];
    __shared__ __align__(16) __nv_bfloat16 Hs[2][2][16][136];
    int tid = threadIdx.x, lane = tid & 31, wid = tid >> 5;
    int n0 = blockIdx.x * 128, i0 = blockIdx.y * 128;
    int bt = blockIdx.z;
    int b = bt >> 7, t = bt & 127;
    int nk = (t < 7 ? t : 7) + 1;
    int C = nk * 16;  // chunks of 16 j
    int wm = wid & 3, wn = wid >> 2;
    int m0w = wm * 32, n0w = wn * 64;
    float cacc[2][8][4];
#pragma unroll
    for (int a = 0; a < 2; a++)
#pragma unroll
        for (int bb = 0; bb < 8; bb++)
#pragma unroll
            for (int q = 0; q < 4; q++) cacc[a][bb][q] = 0.f;

    int crow = tid >> 4, cseg = tid & 15;
    const __nv_bfloat16* Ab = g_Apk + ((size_t)(b * 8) * 2) * 65536;
    const __nv_bfloat16* Hb = g_Hpk + ((size_t)(b * 128) * 2) * 65536;

    auto issue = [&](int cc, int buf) {
        int k = cc >> 4, j0 = (cc & 15) * 16, ts = t - k;
        const __nv_bfloat16* ap =
            Ab + ((size_t)k * 2) * 65536 + (size_t)(j0 + crow) * 256 + i0 + cseg * 8;
        const __nv_bfloat16* hp =
            Hb + ((size_t)ts * 2) * 65536 + (size_t)(j0 + crow) * 256 + n0 + cseg * 8;
        cp_async16(&As[buf][0][crow][cseg * 8], ap);
        cp_async16(&As[buf][1][crow][cseg * 8], ap + 65536);
        cp_async16(&Hs[buf][0][crow][cseg * 8], hp);
        cp_async16(&Hs[buf][1][crow][cseg * 8], hp + 65536);
        asm volatile("cp.async.commit_group;");
    };
    issue(0, 0);

    int krA = (lane & 7) + ((lane >> 4) << 3);
    int mcA = m0w + (lane & 8);
    int krB = (lane & 7) + (lane & 8);
    int ncB = n0w + ((lane >> 4) << 3);

    for (int cc = 0; cc < C; cc++) {
        int buf = cc & 1;
        asm volatile("cp.async.wait_group 0;");
        __syncthreads();
        if (cc + 1 < C) issue(cc + 1, (cc + 1) & 1);

        uint32_t Af[2][2][4];  // [pl][mt][4]
#pragma unroll
        for (int pl = 0; pl < 2; pl++)
#pragma unroll
            for (int mt = 0; mt < 2; mt++) {
                uint32_t ad = smem_u32(&As[buf][pl][krA][mcA + mt * 16]);
                LDSM_T(Af[pl][mt][0], Af[pl][mt][1], Af[pl][mt][2], Af[pl][mt][3], ad);
            }
        uint32_t Bf[8][2];  // one plane at a time (register diet)
#pragma unroll
        for (int p = 0; p < 4; p++) {
            uint32_t r0, r1, r2, r3;
            uint32_t bd = smem_u32(&Hs[buf][0][krB][ncB + p * 16]);
            LDSM_T(r0, r1, r2, r3, bd);
            Bf[2 * p][0] = r0;
            Bf[2 * p][1] = r1;
            Bf[2 * p + 1][0] = r2;
            Bf[2 * p + 1][1] = r3;
        }
#pragma unroll
        for (int mt = 0; mt < 2; mt++)
#pragma unroll
            for (int nt = 0; nt < 8; nt++) {
                mma_bf16(cacc[mt][nt], Af[0][mt], Bf[nt]);  // Ah*Bh
                mma_bf16(cacc[mt][nt], Af[1][mt], Bf[nt]);  // Al*Bh
            }
#pragma unroll
        for (int p = 0; p < 4; p++) {
            uint32_t r0, r1, r2, r3;
            uint32_t bd = smem_u32(&Hs[buf][1][krB][ncB + p * 16]);
            LDSM_T(r0, r1, r2, r3, bd);
            Bf[2 * p][0] = r0;
            Bf[2 * p][1] = r1;
            Bf[2 * p + 1][0] = r2;
            Bf[2 * p + 1][1] = r3;
        }
#pragma unroll
        for (int mt = 0; mt < 2; mt++)
#pragma unroll
            for (int nt = 0; nt < 8; nt++) mma_bf16(cacc[mt][nt], Af[0][mt], Bf[nt]);  // Ah*Bl
    }

    // store packed agg hi/lo: g_aggpk[bt][pl][i][hh]
    int rbase = i0 + m0w + (lane >> 2);
    int cbase = n0 + n0w + (lane & 3) * 2;
    __nv_bfloat16* hipl = g_aggpk + ((size_t)bt * 2) * 65536;
    __nv_bfloat16* lopl = hipl + 65536;
#pragma unroll
    for (int mt = 0; mt < 2; mt++)
#pragma unroll
        for (int nt = 0; nt < 8; nt++) {
            int r = rbase + mt * 16;
            int cl = cbase + nt * 8;
#pragma unroll
            for (int s = 0; s < 2; s++) {
                float v0 = cacc[mt][nt][s * 2], v1 = cacc[mt][nt][s * 2 + 1];
                __nv_bfloat162 h2 = __floats2bfloat162_rn(v0, v1);
                __nv_bfloat162 l2 = __floats2bfloat162_rn(v0 - __bfloat162float(h2.x),
                                                          v1 - __bfloat162float(h2.y));
                size_t off = (size_t)(r + s * 8) * 256 + cl;
                *(__nv_bfloat162*)(hipl + off) = h2;
                *(__nv_bfloat162*)(lopl + off) = l2;
            }
        }
}

// ---------------------------------------------------------------------------
// k_outmma: res = agg @ out_w + out_b + h_t ; LN ; gelu ; transposed store
// ---------------------------------------------------------------------------
__global__ __launch_bounds__(256, 2) void k_outmma(const float* __restrict__ out_b,
                                                   const float* __restrict__ ln_g,
                                                   const float* __restrict__ ln_b,
                                                   float* __restrict__ out) {
    __shared__ __align__(16) __nv_bfloat16 As[2][2][64][24];   // agg tile [row][k16] pad24
    __shared__ __align__(16) __nv_bfloat16 Bs[2][2][16][264];  // W tile [k][col] pad264
    __shared__ float redS[64][4][2];
    int tid = threadIdx.x, lane = tid & 31, wid = tid >> 5;
    int m0 = blockIdx.x * 64;
    int bt = m0 >> 8;
    int i0 = m0 & 255;
    int b = bt >> 7, t = bt & 127;
    int wm = wid & 1, wn = wid >> 1;  // 2 m-warps x 4 n-warps
    int m0w = wm * 32, n0w = wn * 64;
    float cacc[2][8][4];
#pragma unroll
    for (int a = 0; a < 2; a++)
#pragma unroll
        for (int bb = 0; bb < 8; bb++)
#pragma unroll
            for (int q = 0; q < 4; q++) cacc[a][bb][q] = 0.f;

    const __nv_bfloat16* Agg = g_aggpk + ((size_t)bt * 2) * 65536;

    int aPl = tid >> 7, aRow = (tid >> 1) & 63, aSeg = tid & 1;
    auto issue = [&](int cc, int buf) {
        int k0 = cc * 16;
        cp_async16(&As[buf][aPl][aRow][aSeg * 8],
                   Agg + (size_t)aPl * 65536 + (size_t)(i0 + aRow) * 256 + k0 + aSeg * 8);
#pragma unroll
        for (int q = 0; q < 4; q++) {
            int idx = tid + q * 256;
            int pl = idx >> 9, krow = (idx >> 5) & 15, seg = idx & 31;
            cp_async16(&Bs[buf][pl][krow][seg * 8],
                       g_Wpk + pl * 65536 + (size_t)(k0 + krow) * 256 + seg * 8);
        }
        asm volatile("cp.async.commit_group;");
    };
    issue(0, 0);

    int mrA = (lane & 15);
    int kcA = (lane >> 4) * 8;
    int krB = (lane & 7) + (lane & 8);
    int ncB = n0w + ((lane >> 4) << 3);

    for (int cc = 0; cc < 16; cc++) {
        int buf = cc & 1;
        asm volatile("cp.async.wait_group 0;");
        __syncthreads();
        if (cc + 1 < 16) issue(cc + 1, (cc + 1) & 1);

        uint32_t Af[2][2][4];  // [pl][mt][4]  (non-trans: A row-major [m][k])
#pragma unroll
        for (int pl = 0; pl < 2; pl++)
#pragma unroll
            for (int mt = 0; mt < 2; mt++) {
                uint32_t ad = smem_u32(&As[buf][pl][m0w + mt * 16 + mrA][kcA]);
                LDSM_N(Af[pl][mt][0], Af[pl][mt][1], Af[pl][mt][2], Af[pl][mt][3], ad);
            }
        uint32_t Bf[8][2];
#pragma unroll
        for (int p = 0; p < 4; p++) {
            uint32_t r0, r1, r2, r3;
            uint32_t bd = smem_u32(&Bs[buf][0][krB][ncB + p * 16]);
            LDSM_T(r0, r1, r2, r3, bd);
            Bf[2 * p][0] = r0;
            Bf[2 * p][1] = r1;
            Bf[2 * p + 1][0] = r2;
            Bf[2 * p + 1][1] = r3;
        }
#pragma unroll
        for (int mt = 0; mt < 2; mt++)
#pragma unroll
            for (int nt = 0; nt < 8; nt++) {
                mma_bf16(cacc[mt][nt], Af[0][mt], Bf[nt]);
                mma_bf16(cacc[mt][nt], Af[1][mt], Bf[nt]);
            }
#pragma unroll
        for (int p = 0; p < 4; p++) {
            uint32_t r0, r1, r2, r3;
            uint32_t bd = smem_u32(&Bs[buf][1][krB][ncB + p * 16]);
            LDSM_T(r0, r1, r2, r3, bd);
            Bf[2 * p][0] = r0;
            Bf[2 * p][1] = r1;
            Bf[2 * p + 1][0] = r2;
            Bf[2 * p + 1][1] = r3;
        }
#pragma unroll
        for (int mt = 0; mt < 2; mt++)
#pragma unroll
            for (int nt = 0; nt < 8; nt++) mma_bf16(cacc[mt][nt], Af[0][mt], Bf[nt]);
    }

    // ---- epilogue: bias + residual(from Hpk hi+lo) + LN + gelu + store ----
    const __nv_bfloat16* Rh = g_Hpk + ((size_t)(b * Tt + t) * 2) * 65536;
    const __nv_bfloat16* Rl = Rh + 65536;
    float obr[16], lgr[16], lbr[16];
#pragma unroll
    for (int nt = 0; nt < 8; nt++) {
        int c = n0w + nt * 8 + (lane & 3) * 2;
        obr[nt * 2] = out_b[c];
        obr[nt * 2 + 1] = out_b[c + 1];
        lgr[nt * 2] = ln_g[c];
        lgr[nt * 2 + 1] = ln_g[c + 1];
        lbr[nt * 2] = ln_b[c];
        lbr[nt * 2 + 1] = ln_b[c + 1];
    }
    float vv[2][8][4];
    float rsum[4] = {}, rsq[4] = {};
#pragma unroll
    for (int mt = 0; mt < 2; mt++)
#pragma unroll
        for (int s = 0; s < 2; s++) {
            int rloc = m0w + mt * 16 + s * 8 + (lane >> 2);
            int i = i0 + rloc;
#pragma unroll
            for (int nt = 0; nt < 8; nt++) {
                int c = n0w + nt * 8 + (lane & 3) * 2;
                size_t off = (size_t)i * 256 + c;
                __nv_bfloat162 rh = *(const __nv_bfloat162*)(Rh + off);
                __nv_bfloat162 rl = *(const __nv_bfloat162*)(Rl + off);
                float v0 = cacc[mt][nt][s * 2] + obr[nt * 2] +
                           __bfloat162float(rh.x) + __bfloat162float(rl.x);
                float v1 = cacc[mt][nt][s * 2 + 1] + obr[nt * 2 + 1] +
                           __bfloat162float(rh.y) + __bfloat162float(rl.y);
                vv[mt][nt][s * 2] = v0;
                vv[mt][nt][s * 2 + 1] = v1;
                int ri = mt * 2 + s;
                rsum[ri] += v0 + v1;
                rsq[ri] += v0 * v0 + v1 * v1;
            }
        }
#pragma unroll
    for (int ri = 0; ri < 4; ri++) {
#pragma unroll
        for (int o = 1; o < 4; o <<= 1) {
            rsum[ri] += __shfl_xor_sync(0xffffffffu, rsum[ri], o);
            rsq[ri] += __shfl_xor_sync(0xffffffffu, rsq[ri], o);
        }
    }
    if ((lane & 3) == 0) {
#pragma unroll
        for (int mt = 0; mt < 2; mt++)
#pragma unroll
            for (int s = 0; s < 2; s++) {
                int rloc = m0w + mt * 16 + s * 8 + (lane >> 2);
                redS[rloc][wn][0] = rsum[mt * 2 + s];
                redS[rloc][wn][1] = rsq[mt * 2 + s];
            }
    }
    __syncthreads();
#pragma unroll
    for (int mt = 0; mt < 2; mt++)
#pragma unroll
        for (int s = 0; s < 2; s++) {
            int rloc = m0w + mt * 16 + s * 8 + (lane >> 2);
            int i = i0 + rloc;
            float su = redS[rloc][0][0] + redS[rloc][1][0] + redS[rloc][2][0] + redS[rloc][3][0];
            float sq = redS[rloc][0][1] + redS[rloc][1][1] + redS[rloc][2][1] + redS[rloc][3][1];
            float mu = su * (1.f / 256.f);
            float var = sq * (1.f / 256.f) - mu * mu;
            float rstd = rsqrtf(var + 1e-5f);
            float* ob = out + (((size_t)(b * Nn + i)) * Tt + t) * Hh;
#pragma unroll
            for (int nt = 0; nt < 8; nt++) {
                int c = n0w + nt * 8 + (lane & 3) * 2;
                float w0 = gelu_exact((vv[mt][nt][s * 2] - mu) * rstd * lgr[nt * 2] + lbr[nt * 2]);
                float w1 = gelu_exact((vv[mt][nt][s * 2 + 1] - mu) * rstd * lgr[nt * 2 + 1] +
                                      lbr[nt * 2 + 1]);
                *(float2*)(ob + c) = make_float2(w0, w1);
            }
        }
}

// ---------------------------------------------------------------------------
extern "C" void kernel_launch(void* const* d_in, const int* in_sizes, int n_in,
                              void* d_out, int out_size) {
    (void)in_sizes;
    (void)n_in;
    (void)out_size;
    const float* x = (const float*)d_in[0];
    const float* A_list = (const float*)d_in[1];
    const float* in_w = (const float*)d_in[2];
    const float* in_b = (const float*)d_in[3];
    const float* out_w = (const float*)d_in[4];
    const float* out_b = (const float*)d_in[5];
    const float* lag_embed = (const float*)d_in[6];
    const float* ctx_w1 = (const float*)d_in[7];
    const float* ctx_b1 = (const float*)d_in[8];
    const float* ctx_w2 = (const float*)d_in[9];
    const float* ctx_b2 = (const float*)d_in[10];
    const float* gate_w1 = (const float*)d_in[11];
    const float* gate_b1 = (const float*)d_in[12];
    const float* gate_w2 = (const float*)d_in[13];
    const float* gate_b2 = (const float*)d_in[14];
    const float* ln_g = (const float*)d_in[15];
    const float* ln_b = (const float*)d_in[16];
    float* out = (float*)d_out;

    k_ctxanorm<<<4 + (Kk * Nn) / 2, 512>>>(x, A_list);
    k_ingemm<<<dim3(2, 1024), 256>>>(x, in_w, in_b);
    k_packA<<<Bq * Kk, 256>>>(lag_embed, ctx_w1, ctx_b1, ctx_w2, ctx_b2,
                              gate_w1, gate_b1, gate_w2, gate_b2);
    k_lagmma<<<dim3(2, 2, Bq * Tt), 256>>>();  // launch index 3 -> ncu capture
    k_packW<<<Hh, Hh>>>(out_w);
    k_outmma<<<(Bq * Tt * Nn) / 64, 256>>>(out_b, ln_g, ln_b, out);
}